// round 1
// baseline (speedup 1.0000x reference)
#include <cuda_runtime.h>
#include <cuda_bf16.h>
#include <cstdint>

#define BB    64
#define TT    512
#define HID   256
#define DI    512
#define DS    16
#define NHH   8
#define HD    64
#define DCONV 4
#define CCH   544    // DI + 2*DS
#define PROJ  1064   // 2*DI + 2*DS + NH
#define ROWS  (BB*TT) // 32768

// ---------------- scratch (device globals; no allocation allowed) ----------
__device__ float g_xn[ROWS * HID];        //  33.5 MB
__device__ float g_zx[ROWS * PROJ];       // 139.5 MB
__device__ float g_xbc[ROWS * CCH];       //  71.3 MB
__device__ float g_y[ROWS * DI];          //  67.1 MB
__device__ float g_tout[ROWS * HID];      //  33.5 MB

// ---------------- helpers ---------------------------------------------------
__device__ __forceinline__ float siluf(float x) { return x / (1.f + __expf(-x)); }
__device__ __forceinline__ float softplusf(float x) {
    return (x > 20.f) ? x : log1pf(__expf(x));
}
__device__ __forceinline__ float sigmoidf_(float x) { return 1.f / (1.f + __expf(-x)); }
__device__ __forceinline__ float warpSum(float v) {
#pragma unroll
    for (int o = 16; o; o >>= 1) v += __shfl_xor_sync(0xffffffffu, v, o);
    return v;
}

// ---------------- 1) rmsnorm of tokens -------------------------------------
__global__ void rmsnorm_k(const float* __restrict__ x, const float* __restrict__ w,
                          float* __restrict__ out) {
    int r = blockIdx.x;
    int tid = threadIdx.x;                 // 64 threads, 4 elems each
    const float4* xr = (const float4*)(x + (size_t)r * HID);
    float4 v = xr[tid];
    float ss = v.x*v.x + v.y*v.y + v.z*v.z + v.w*v.w;
    ss = warpSum(ss);
    __shared__ float red[2];
    if ((tid & 31) == 0) red[tid >> 5] = ss;
    __syncthreads();
    float tot = red[0] + red[1];
    float sc = rsqrtf(tot / HID + 1e-5f);
    const float4* wr = (const float4*)w;
    float4 wv = wr[tid];
    float4 o;
    o.x = v.x * sc * wv.x; o.y = v.y * sc * wv.y;
    o.z = v.z * sc * wv.z; o.w = v.w * sc * wv.w;
    ((float4*)(out + (size_t)r * HID))[tid] = o;
}

// ---------------- 2) generic SGEMM: C = A@W + bias (+res) -------------------
// A: MxK row-major, W: KxN row-major. Block tile 64x64, BK=16, 256 threads, 4x4 micro.
__global__ __launch_bounds__(256) void gemm_k(
    const float* __restrict__ A, const float* __restrict__ W,
    const float* __restrict__ bias, const float* __restrict__ res,
    float* __restrict__ C, int M, int K, int N)
{
    __shared__ float As[64][16];
    __shared__ float Ws[16][64];
    int bm = blockIdx.y * 64, bn = blockIdx.x * 64;
    int tid = threadIdx.x;
    int tx = tid & 15, ty = tid >> 4;
    float acc[4][4];
#pragma unroll
    for (int i = 0; i < 4; i++)
#pragma unroll
        for (int j = 0; j < 4; j++) acc[i][j] = 0.f;

    int colA = tid & 15, rowA = tid >> 4;      // A tile loader
    int colW = tid & 63, rowW = tid >> 6;      // W tile loader

    for (int k0 = 0; k0 < K; k0 += 16) {
#pragma unroll
        for (int i = 0; i < 4; i++) {
            int m = bm + rowA + 16 * i;        // M % 64 == 0 always here
            As[rowA + 16 * i][colA] = A[(size_t)m * K + k0 + colA];
        }
#pragma unroll
        for (int i = 0; i < 4; i++) {
            int kk = rowW + 4 * i;
            int n = bn + colW;
            Ws[kk][colW] = (n < N) ? W[(size_t)(k0 + kk) * N + n] : 0.f;
        }
        __syncthreads();
#pragma unroll
        for (int kk = 0; kk < 16; kk++) {
            float a[4];
            float4 wv = *((const float4*)&Ws[kk][tx * 4]);
#pragma unroll
            for (int i = 0; i < 4; i++) a[i] = As[ty * 4 + i][kk];
            float w4[4] = {wv.x, wv.y, wv.z, wv.w};
#pragma unroll
            for (int i = 0; i < 4; i++)
#pragma unroll
                for (int j = 0; j < 4; j++) acc[i][j] = fmaf(a[i], w4[j], acc[i][j]);
        }
        __syncthreads();
    }
#pragma unroll
    for (int i = 0; i < 4; i++) {
        int m = bm + ty * 4 + i;
#pragma unroll
        for (int j = 0; j < 4; j++) {
            int n = bn + tx * 4 + j;
            if (n < N) {
                float v = acc[i][j] + bias[n];
                if (res) v += res[(size_t)m * N + n];
                C[(size_t)m * N + n] = v;
            }
        }
    }
}

// ---------------- 3) causal depthwise conv + silu ---------------------------
__global__ void conv_k(const float* __restrict__ zx, const float* __restrict__ cw,
                       const float* __restrict__ cb, float* __restrict__ out) {
    int idx = blockIdx.x * blockDim.x + threadIdx.x;
    int total = ROWS * CCH;
    if (idx >= total) return;
    int c = idx % CCH;
    int row = idx / CCH;
    int t = row % TT;
    int b = row / TT;
    float acc = cb[c];
#pragma unroll
    for (int k = 0; k < DCONV; k++) {
        int tt = t - (DCONV - 1) + k;
        if (tt >= 0)
            acc = fmaf(zx[((size_t)(b * TT + tt)) * PROJ + DI + c], cw[k * CCH + c], acc);
    }
    out[(size_t)row * CCH + c] = siluf(acc);
}

// ---------------- 4) SSM scan ----------------------------------------------
// grid (NH, B), block 64. Thread d owns 16 states. B/C via warp shuffles.
__global__ __launch_bounds__(64) void scan_k(
    const float* __restrict__ xbc, const float* __restrict__ zx,
    const float* __restrict__ dt_bias, const float* __restrict__ A_log,
    const float* __restrict__ Dp, float* __restrict__ y)
{
    int h = blockIdx.x, b = blockIdx.y;
    int d = threadIdx.x;
    int lane = d & 31;
    float A = -__expf(A_log[h]);
    float Dh = Dp[h];
    float dtb = dt_bias[h];
    float hreg[DS];
#pragma unroll
    for (int s = 0; s < DS; s++) hreg[s] = 0.f;

    size_t rowbase = (size_t)b * TT;
    const float* xb  = xbc + rowbase * CCH;
    const float* dtp = zx + rowbase * PROJ + (2 * DI + 2 * DS) + h;  // col 1056+h
    float* yrow = y + rowbase * DI + h * HD + d;

    float xc  = xb[h * HD + d];
    float bcc = xb[DI + lane];
    float dtc = dtp[0];

    for (int t = 0; t < TT; t++) {
        int tn = (t + 1 < TT) ? t + 1 : (TT - 1);
        float xnx = xb[(size_t)tn * CCH + h * HD + d];
        float bcn = xb[(size_t)tn * CCH + DI + lane];
        float dtn = dtp[(size_t)tn * PROJ];

        float dtsp = softplusf(dtc + dtb);
        float dA = __expf(dtsp * A);
        float dtx = dtsp * xc;
        float yv = Dh * xc;
#pragma unroll
        for (int s = 0; s < DS; s++) {
            float Bs = __shfl_sync(0xffffffffu, bcc, s);
            float Cs = __shfl_sync(0xffffffffu, bcc, DS + s);
            hreg[s] = fmaf(hreg[s], dA, dtx * Bs);
            yv = fmaf(hreg[s], Cs, yv);
        }
        yrow[(size_t)t * DI] = yv;
        xc = xnx; bcc = bcn; dtc = dtn;
    }
}

// ---------------- 5) gate + rmsnorm (in place on y) -------------------------
__global__ void gatenorm_k(float* __restrict__ y, const float* __restrict__ zx,
                           const float* __restrict__ gw) {
    int r = blockIdx.x;
    int tid = threadIdx.x;                 // 128 threads x 4
    float4 yv = ((const float4*)(y + (size_t)r * DI))[tid];
    float4 zv = ((const float4*)(zx + (size_t)r * PROJ))[tid];
    float4 g;
    g.x = yv.x * siluf(zv.x); g.y = yv.y * siluf(zv.y);
    g.z = yv.z * siluf(zv.z); g.w = yv.w * siluf(zv.w);
    float ss = g.x*g.x + g.y*g.y + g.z*g.z + g.w*g.w;
    ss = warpSum(ss);
    __shared__ float red[4];
    if ((tid & 31) == 0) red[tid >> 5] = ss;
    __syncthreads();
    float tot = red[0] + red[1] + red[2] + red[3];
    float sc = rsqrtf(tot / DI + 1e-5f);
    float4 wv = ((const float4*)gw)[tid];
    float4 o;
    o.x = g.x * sc * wv.x; o.y = g.y * sc * wv.y;
    o.z = g.z * sc * wv.z; o.w = g.w * sc * wv.w;
    ((float4*)(y + (size_t)r * DI))[tid] = o;
}

// ---------------- 7) Kalman head -------------------------------------------
__global__ __launch_bounds__(64) void kalman_k(
    const float* __restrict__ tout, const float* __restrict__ z_t,
    const float* __restrict__ init_state,
    const float* __restrict__ kp_w1, const float* __restrict__ kp_b1,
    const float* __restrict__ kp_w2, const float* __restrict__ kp_b2,
    const float* __restrict__ km_w1, const float* __restrict__ km_b1,
    const float* __restrict__ km_w2, const float* __restrict__ km_b2,
    const float* __restrict__ kg_w1, const float* __restrict__ kg_b1,
    const float* __restrict__ kg_w2, const float* __restrict__ kg_b2,
    const float* __restrict__ kW, float* __restrict__ out)
{
    __shared__ float sp[HID];
    __shared__ float redv[2], redg[2];
    int r = blockIdx.x;
    int t = r % TT;
    int tid = threadIdx.x;                 // 64 threads
    const float* prow = (t == 0) ? init_state : (tout + (size_t)(r - 1) * HID);
    ((float4*)sp)[tid] = ((const float4*)prow)[tid];
    float z = z_t[r];
    __syncthreads();

    float ap = kp_b1[tid];
    float ag = kg_b1[tid];
#pragma unroll 8
    for (int i = 0; i < HID; i++) {
        float v = sp[i];
        ap = fmaf(v, kp_w1[i * 64 + tid], ap);
        ag = fmaf(v, kg_w1[i * 64 + tid], ag);
    }
    ag = fmaf(z, kg_w1[HID * 64 + tid], ag);
    float vp = siluf(ap) * kp_w2[tid];
    float gp = siluf(ag) * kg_w2[tid];
    vp = warpSum(vp);
    gp = warpSum(gp);
    if ((tid & 31) == 0) { redv[tid >> 5] = vp; redg[tid >> 5] = gp; }
    __syncthreads();
    if (tid == 0) {
        float v_prior = softplusf(redv[0] + redv[1] + kp_b2[0]);
        float Kt = sigmoidf_(redg[0] + redg[1] + kg_b2[0]);
        float macc = km_b2[0];
#pragma unroll
        for (int k = 0; k < 32; k++)
            macc = fmaf(siluf(fmaf(z, km_w1[k], km_b1[k])), km_w2[k], macc);
        float m_t = softplusf(macc);
        float vpost = v_prior + Kt * (m_t - kW[0] * v_prior);
        vpost = fminf(fmaxf(vpost, 1e-6f), 10.f);
        out[r] = vpost;
    }
}

// ---------------- 8) per-batch softmax reductions ---------------------------
__global__ void reduce_k(float* __restrict__ out) {
    __shared__ float sa[256], sb[256];
    int b = blockIdx.x;
    int tid = threadIdx.x;                 // 256 threads, 2 elems each
    const float* v = out + (size_t)b * TT;
    float v0 = v[tid], v1 = v[tid + 256];

    sa[tid] = fmaxf(v0, v1);
    sb[tid] = fminf(v0, v1);
    __syncthreads();
    for (int s = 128; s > 0; s >>= 1) {
        if (tid < s) {
            sa[tid] = fmaxf(sa[tid], sa[tid + s]);
            sb[tid] = fminf(sb[tid], sb[tid + s]);
        }
        __syncthreads();
    }
    float mx = sa[0], mn = sb[0];
    __syncthreads();

    // softmax(+v): weights exp(v - mx)
    float e0 = __expf(v0 - mx), e1 = __expf(v1 - mx);
    sa[tid] = e0 + e1;
    sb[tid] = e0 * v0 + e1 * v1;
    __syncthreads();
    for (int s = 128; s > 0; s >>= 1) {
        if (tid < s) { sa[tid] += sa[tid + s]; sb[tid] += sb[tid + s]; }
        __syncthreads();
    }
    float spden = sa[0], spnum = sb[0];
    __syncthreads();

    // softmax(-v): weights exp(mn - v)
    float f0 = __expf(mn - v0), f1 = __expf(mn - v1);
    sa[tid] = f0 + f1;
    sb[tid] = f0 * v0 + f1 * v1;
    __syncthreads();
    for (int s = 128; s > 0; s >>= 1) {
        if (tid < s) { sa[tid] += sa[tid + s]; sb[tid] += sb[tid + s]; }
        __syncthreads();
    }
    if (tid == 0) {
        out[ROWS + b] = spnum / spden;
        out[ROWS + BB + b] = sb[0] / sa[0];
    }
}

// ---------------- launcher ---------------------------------------------------
extern "C" void kernel_launch(void* const* d_in, const int* in_sizes, int n_in,
                              void* d_out, int out_size) {
    const float* tokens   = (const float*)d_in[0];
    const float* z_t      = (const float*)d_in[1];
    const float* norm_w   = (const float*)d_in[2];
    const float* in_w     = (const float*)d_in[3];
    const float* in_b     = (const float*)d_in[4];
    const float* conv_w   = (const float*)d_in[5];
    const float* conv_b   = (const float*)d_in[6];
    const float* dt_bias  = (const float*)d_in[7];
    const float* A_log    = (const float*)d_in[8];
    const float* Dp       = (const float*)d_in[9];
    const float* gnorm_w  = (const float*)d_in[10];
    const float* out_w    = (const float*)d_in[11];
    const float* out_b    = (const float*)d_in[12];
    const float* kp_w1    = (const float*)d_in[13];
    const float* kp_b1    = (const float*)d_in[14];
    const float* kp_w2    = (const float*)d_in[15];
    const float* kp_b2    = (const float*)d_in[16];
    const float* km_w1    = (const float*)d_in[17];
    const float* km_b1    = (const float*)d_in[18];
    const float* km_w2    = (const float*)d_in[19];
    const float* km_b2    = (const float*)d_in[20];
    const float* kg_w1    = (const float*)d_in[21];
    const float* kg_b1    = (const float*)d_in[22];
    const float* kg_w2    = (const float*)d_in[23];
    const float* kg_b2    = (const float*)d_in[24];
    const float* kW       = (const float*)d_in[25];
    const float* init_st  = (const float*)d_in[26];
    float* out = (float*)d_out;

    float *xn, *zx, *xbc, *y, *tout;
    cudaGetSymbolAddress((void**)&xn,   g_xn);
    cudaGetSymbolAddress((void**)&zx,   g_zx);
    cudaGetSymbolAddress((void**)&xbc,  g_xbc);
    cudaGetSymbolAddress((void**)&y,    g_y);
    cudaGetSymbolAddress((void**)&tout, g_tout);

    // 1) rmsnorm
    rmsnorm_k<<<ROWS, 64>>>(tokens, norm_w, xn);
    // 2) in-proj GEMM (32768x256 @ 256x1064)
    gemm_k<<<dim3((PROJ + 63) / 64, ROWS / 64), 256>>>(xn, in_w, in_b, nullptr, zx,
                                                       ROWS, HID, PROJ);
    // 3) conv + silu
    {
        int total = ROWS * CCH;
        conv_k<<<(total + 255) / 256, 256>>>(zx, conv_w, conv_b, xbc);
    }
    // 4) scan
    scan_k<<<dim3(NHH, BB), 64>>>(xbc, zx, dt_bias, A_log, Dp, y);
    // 5) gate + rmsnorm
    gatenorm_k<<<ROWS, 128>>>(y, zx, gnorm_w);
    // 6) out-proj GEMM + residual (32768x512 @ 512x256)
    gemm_k<<<dim3(HID / 64, ROWS / 64), 256>>>(y, out_w, out_b, tokens, tout,
                                               ROWS, DI, HID);
    // 7) Kalman head -> v_post into out[0:32768]
    kalman_k<<<ROWS, 64>>>(tout, z_t, init_st,
                           kp_w1, kp_b1, kp_w2, kp_b2,
                           km_w1, km_b1, km_w2, km_b2,
                           kg_w1, kg_b1, kg_w2, kg_b2, kW, out);
    // 8) per-batch reductions -> out[32768:32832], out[32832:32896]
    reduce_k<<<BB, 256>>>(out);
}

// round 2
// speedup vs baseline: 1.3062x; 1.3062x over previous
#include <cuda_runtime.h>
#include <cuda_bf16.h>
#include <cstdint>

#define BB    64
#define TT    512
#define HID   256
#define DI    512
#define DS    16
#define NHH   8
#define HD    64
#define DCONV 4
#define CCH   544    // DI + 2*DS
#define PROJ  1064   // 2*DI + 2*DS + NH
#define ROWS  (BB*TT) // 32768
#define NC    8
#define LC    64     // TT/NC

// ---------------- scratch (device globals; no allocation allowed) ----------
__device__ float g_xn[ROWS * HID];
__device__ float g_zx[ROWS * PROJ];
__device__ float g_xbc[ROWS * CCH];
__device__ float g_y[ROWS * DI];
__device__ float g_tout[ROWS * HID];
__device__ float g_hloc[BB * NHH * NC * HD * DS];    // 16.8 MB
__device__ float g_hstart[BB * NHH * NC * HD * DS];  // 16.8 MB
__device__ float g_cum[BB * NHH * TT];               // 1 MB

// ---------------- helpers ---------------------------------------------------
__device__ __forceinline__ float siluf(float x) { return x / (1.f + __expf(-x)); }
__device__ __forceinline__ float softplusf(float x) {
    return (x > 20.f) ? x : log1pf(__expf(x));
}
__device__ __forceinline__ float sigmoidf_(float x) { return 1.f / (1.f + __expf(-x)); }
__device__ __forceinline__ float warpSum(float v) {
#pragma unroll
    for (int o = 16; o; o >>= 1) v += __shfl_xor_sync(0xffffffffu, v, o);
    return v;
}

// ---------------- 1) rmsnorm of tokens -------------------------------------
__global__ void rmsnorm_k(const float* __restrict__ x, const float* __restrict__ w,
                          float* __restrict__ out) {
    int r = blockIdx.x;
    int tid = threadIdx.x;                 // 64 threads, 4 elems each
    const float4* xr = (const float4*)(x + (size_t)r * HID);
    float4 v = xr[tid];
    float ss = v.x*v.x + v.y*v.y + v.z*v.z + v.w*v.w;
    ss = warpSum(ss);
    __shared__ float red[2];
    if ((tid & 31) == 0) red[tid >> 5] = ss;
    __syncthreads();
    float tot = red[0] + red[1];
    float sc = rsqrtf(tot / HID + 1e-5f);
    float4 wv = ((const float4*)w)[tid];
    float4 o;
    o.x = v.x * sc * wv.x; o.y = v.y * sc * wv.y;
    o.z = v.z * sc * wv.z; o.w = v.w * sc * wv.w;
    ((float4*)(out + (size_t)r * HID))[tid] = o;
}

// ---------------- 2) SGEMM 128x128 tile, BK=16, 256 thr, 8x8 micro ----------
__global__ __launch_bounds__(256, 2) void gemm128_k(
    const float* __restrict__ A, const float* __restrict__ W,
    const float* __restrict__ bias, const float* __restrict__ res,
    float* __restrict__ C, int M, int K, int N)
{
    __shared__ float As[16][132];   // [k][m], transposed
    __shared__ float Ws[16][132];   // [k][n]
    int bm = blockIdx.y * 128, bn = blockIdx.x * 128;
    int tid = threadIdx.x;
    int tx = tid & 15, ty = tid >> 4;

    int arow = tid >> 2;            // 0..63 (second at +64)
    int ac4  = tid & 3;             // k-quad
    int wrow = tid >> 5;            // 0..7 (second at +8)
    int wc4  = tid & 31;            // n-quad

    float4 apre0, apre1, wpre0, wpre1;
    {
        apre0 = *(const float4*)&A[(size_t)(bm + arow) * K + ac4 * 4];
        apre1 = *(const float4*)&A[(size_t)(bm + arow + 64) * K + ac4 * 4];
        int n4 = bn + wc4 * 4;
        if (n4 < N) {
            wpre0 = *(const float4*)&W[(size_t)wrow * N + n4];
            wpre1 = *(const float4*)&W[(size_t)(wrow + 8) * N + n4];
        } else {
            wpre0 = make_float4(0.f, 0.f, 0.f, 0.f);
            wpre1 = wpre0;
        }
    }

    float acc[8][8];
#pragma unroll
    for (int i = 0; i < 8; i++)
#pragma unroll
        for (int j = 0; j < 8; j++) acc[i][j] = 0.f;

    for (int k0 = 0; k0 < K; k0 += 16) {
        // commit prefetched tile to smem (A transposed)
        As[ac4*4+0][arow] = apre0.x;
        As[ac4*4+1][arow] = apre0.y;
        As[ac4*4+2][arow] = apre0.z;
        As[ac4*4+3][arow] = apre0.w;
        As[ac4*4+0][arow+64] = apre1.x;
        As[ac4*4+1][arow+64] = apre1.y;
        As[ac4*4+2][arow+64] = apre1.z;
        As[ac4*4+3][arow+64] = apre1.w;
        *(float4*)&Ws[wrow][wc4*4]   = wpre0;
        *(float4*)&Ws[wrow+8][wc4*4] = wpre1;
        __syncthreads();

        // prefetch next k-tile (hidden under compute)
        int kn = k0 + 16;
        if (kn < K) {
            apre0 = *(const float4*)&A[(size_t)(bm + arow) * K + kn + ac4 * 4];
            apre1 = *(const float4*)&A[(size_t)(bm + arow + 64) * K + kn + ac4 * 4];
            int n4 = bn + wc4 * 4;
            if (n4 < N) {
                wpre0 = *(const float4*)&W[(size_t)(kn + wrow) * N + n4];
                wpre1 = *(const float4*)&W[(size_t)(kn + wrow + 8) * N + n4];
            }
        }

#pragma unroll
        for (int kk = 0; kk < 16; kk++) {
            float4 a0 = *(const float4*)&As[kk][ty*4];
            float4 a1 = *(const float4*)&As[kk][64 + ty*4];
            float4 b0 = *(const float4*)&Ws[kk][tx*4];
            float4 b1 = *(const float4*)&Ws[kk][64 + tx*4];
            float av[8] = {a0.x,a0.y,a0.z,a0.w,a1.x,a1.y,a1.z,a1.w};
            float bv[8] = {b0.x,b0.y,b0.z,b0.w,b1.x,b1.y,b1.z,b1.w};
#pragma unroll
            for (int i = 0; i < 8; i++)
#pragma unroll
                for (int j = 0; j < 8; j++)
                    acc[i][j] = fmaf(av[i], bv[j], acc[i][j]);
        }
        __syncthreads();
    }

#pragma unroll
    for (int i = 0; i < 8; i++) {
        int m = bm + ((i & 4) ? 64 : 0) + ty * 4 + (i & 3);
#pragma unroll
        for (int j = 0; j < 8; j++) {
            int n = bn + ((j & 4) ? 64 : 0) + tx * 4 + (j & 3);
            if (n < N) {
                float v = acc[i][j] + bias[n];
                if (res) v += res[(size_t)m * N + n];
                C[(size_t)m * N + n] = v;
            }
        }
    }
}

// ---------------- 3) causal depthwise conv + silu ---------------------------
__global__ void conv_k(const float* __restrict__ zx, const float* __restrict__ cw,
                       const float* __restrict__ cb, float* __restrict__ out) {
    int idx = blockIdx.x * blockDim.x + threadIdx.x;
    int total = ROWS * CCH;
    if (idx >= total) return;
    int c = idx % CCH;
    int row = idx / CCH;
    int t = row % TT;
    int b = row / TT;
    float acc = cb[c];
#pragma unroll
    for (int k = 0; k < DCONV; k++) {
        int tt = t - (DCONV - 1) + k;
        if (tt >= 0)
            acc = fmaf(zx[((size_t)(b * TT + tt)) * PROJ + DI + c], cw[k * CCH + c], acc);
    }
    out[(size_t)row * CCH + c] = siluf(acc);
}

// ---------------- 4a) chunked scan: local pass ------------------------------
__global__ __launch_bounds__(64) void scanA_k(
    const float* __restrict__ xbc, const float* __restrict__ zx,
    const float* __restrict__ dt_bias, const float* __restrict__ A_log,
    const float* __restrict__ Dp, float* __restrict__ y,
    float* __restrict__ hloc, float* __restrict__ cum)
{
    __shared__ float sBC[LC][32];
    __shared__ float sdt[LC];
    int h = blockIdx.x, b = blockIdx.y, c = blockIdx.z;
    int d = threadIdx.x;
    int t0 = c * LC;
    size_t rowbase = (size_t)(b * TT + t0);

    for (int i = d; i < LC * 32; i += 64) {
        int t = i >> 5, j = i & 31;
        sBC[t][j] = xbc[(rowbase + t) * CCH + DI + j];
    }
    float dtb = dt_bias[h];
    for (int i = d; i < LC; i += 64)
        sdt[i] = softplusf(zx[(rowbase + i) * PROJ + 2 * DI + 2 * DS + h] + dtb);
    __syncthreads();

    float A = -__expf(A_log[h]);
    float Dh = Dp[h];
    float hr[DS];
#pragma unroll
    for (int s = 0; s < DS; s++) hr[s] = 0.f;
    float cm = 1.f;

    const float* xp = xbc + rowbase * CCH + h * HD + d;
    float* yp = y + rowbase * DI + h * HD + d;
    float* cmp = cum + ((size_t)(b * NHH + h)) * TT + t0;

    for (int t = 0; t < LC; t++) {
        float x = xp[(size_t)t * CCH];
        float dtsp = sdt[t];
        float dA = __expf(dtsp * A);
        cm *= dA;
        if (d == 0) cmp[t] = cm;
        float dtx = dtsp * x;
        float yv = Dh * x;
        float Bv[16], Cv[16];
        *(float4*)&Bv[0]  = *(const float4*)&sBC[t][0];
        *(float4*)&Bv[4]  = *(const float4*)&sBC[t][4];
        *(float4*)&Bv[8]  = *(const float4*)&sBC[t][8];
        *(float4*)&Bv[12] = *(const float4*)&sBC[t][12];
        *(float4*)&Cv[0]  = *(const float4*)&sBC[t][16];
        *(float4*)&Cv[4]  = *(const float4*)&sBC[t][20];
        *(float4*)&Cv[8]  = *(const float4*)&sBC[t][24];
        *(float4*)&Cv[12] = *(const float4*)&sBC[t][28];
#pragma unroll
        for (int s = 0; s < DS; s++) {
            hr[s] = fmaf(hr[s], dA, dtx * Bv[s]);
            yv = fmaf(hr[s], Cv[s], yv);
        }
        yp[(size_t)t * DI] = yv;
    }

    float* hl = hloc + ((size_t)((b * NHH + h) * NC + c)) * (DS * HD);
#pragma unroll
    for (int s = 0; s < DS; s++) hl[s * HD + d] = hr[s];
}

// ---------------- 4b) chunked scan: chain chunk states ----------------------
__global__ __launch_bounds__(64) void scanB_k(const float* __restrict__ hloc,
                                              const float* __restrict__ cum,
                                              float* __restrict__ hstart)
{
    int h = blockIdx.x, b = blockIdx.y, d = threadIdx.x;
    size_t base = (size_t)(b * NHH + h);
    float hs[DS];
#pragma unroll
    for (int s = 0; s < DS; s++) hs[s] = 0.f;
    for (int c = 0; c < NC; c++) {
        float* hsp = hstart + (base * NC + c) * (DS * HD);
#pragma unroll
        for (int s = 0; s < DS; s++) hsp[s * HD + d] = hs[s];
        float P = cum[base * TT + c * LC + LC - 1];
        const float* hl = hloc + (base * NC + c) * (DS * HD);
#pragma unroll
        for (int s = 0; s < DS; s++) hs[s] = fmaf(hs[s], P, hl[s * HD + d]);
    }
}

// ---------------- 4c) chunked scan: correction ------------------------------
__global__ __launch_bounds__(64) void scanC_k(const float* __restrict__ xbc,
                                              const float* __restrict__ hstart,
                                              const float* __restrict__ cum,
                                              float* __restrict__ y)
{
    __shared__ float sC[LC][16];
    __shared__ float scm[LC];
    int h = blockIdx.x, b = blockIdx.y, c = blockIdx.z + 1;
    int d = threadIdx.x;
    int t0 = c * LC;
    size_t rowbase = (size_t)(b * TT + t0);
    size_t base = (size_t)(b * NHH + h);

    for (int i = d; i < LC * 16; i += 64) {
        int t = i >> 4, j = i & 15;
        sC[t][j] = xbc[(rowbase + t) * CCH + DI + DS + j];
    }
    for (int i = d; i < LC; i += 64) scm[i] = cum[base * TT + t0 + i];

    float hs[DS];
    const float* hsp = hstart + (base * NC + c) * (DS * HD);
#pragma unroll
    for (int s = 0; s < DS; s++) hs[s] = hsp[s * HD + d];
    __syncthreads();

    float* yp = y + rowbase * DI + h * HD + d;
    for (int t = 0; t < LC; t++) {
        float Cv[16];
        *(float4*)&Cv[0]  = *(const float4*)&sC[t][0];
        *(float4*)&Cv[4]  = *(const float4*)&sC[t][4];
        *(float4*)&Cv[8]  = *(const float4*)&sC[t][8];
        *(float4*)&Cv[12] = *(const float4*)&sC[t][12];
        float acc = 0.f;
#pragma unroll
        for (int s = 0; s < DS; s++) acc = fmaf(hs[s], Cv[s], acc);
        yp[(size_t)t * DI] += acc * scm[t];
    }
}

// ---------------- 5) gate + rmsnorm (in place on y) -------------------------
__global__ void gatenorm_k(float* __restrict__ y, const float* __restrict__ zx,
                           const float* __restrict__ gw) {
    int r = blockIdx.x;
    int tid = threadIdx.x;                 // 128 threads x 4
    float4 yv = ((const float4*)(y + (size_t)r * DI))[tid];
    float4 zv = ((const float4*)(zx + (size_t)r * PROJ))[tid];
    float4 g;
    g.x = yv.x * siluf(zv.x); g.y = yv.y * siluf(zv.y);
    g.z = yv.z * siluf(zv.z); g.w = yv.w * siluf(zv.w);
    float ss = g.x*g.x + g.y*g.y + g.z*g.z + g.w*g.w;
    ss = warpSum(ss);
    __shared__ float red[4];
    if ((tid & 31) == 0) red[tid >> 5] = ss;
    __syncthreads();
    float tot = red[0] + red[1] + red[2] + red[3];
    float sc = rsqrtf(tot / DI + 1e-5f);
    float4 wv = ((const float4*)gw)[tid];
    float4 o;
    o.x = g.x * sc * wv.x; o.y = g.y * sc * wv.y;
    o.z = g.z * sc * wv.z; o.w = g.w * sc * wv.w;
    ((float4*)(y + (size_t)r * DI))[tid] = o;
}

// ---------------- 7) Kalman head -------------------------------------------
__global__ __launch_bounds__(64) void kalman_k(
    const float* __restrict__ tout, const float* __restrict__ z_t,
    const float* __restrict__ init_state,
    const float* __restrict__ kp_w1, const float* __restrict__ kp_b1,
    const float* __restrict__ kp_w2, const float* __restrict__ kp_b2,
    const float* __restrict__ km_w1, const float* __restrict__ km_b1,
    const float* __restrict__ km_w2, const float* __restrict__ km_b2,
    const float* __restrict__ kg_w1, const float* __restrict__ kg_b1,
    const float* __restrict__ kg_w2, const float* __restrict__ kg_b2,
    const float* __restrict__ kW, float* __restrict__ out)
{
    __shared__ float sp[HID];
    __shared__ float redv[2], redg[2];
    int r = blockIdx.x;
    int t = r % TT;
    int tid = threadIdx.x;                 // 64 threads
    const float* prow = (t == 0) ? init_state : (tout + (size_t)(r - 1) * HID);
    ((float4*)sp)[tid] = ((const float4*)prow)[tid];
    float z = z_t[r];
    __syncthreads();

    float ap = kp_b1[tid];
    float ag = kg_b1[tid];
#pragma unroll 8
    for (int i = 0; i < HID; i++) {
        float v = sp[i];
        ap = fmaf(v, kp_w1[i * 64 + tid], ap);
        ag = fmaf(v, kg_w1[i * 64 + tid], ag);
    }
    ag = fmaf(z, kg_w1[HID * 64 + tid], ag);
    float vp = siluf(ap) * kp_w2[tid];
    float gp = siluf(ag) * kg_w2[tid];
    vp = warpSum(vp);
    gp = warpSum(gp);
    if ((tid & 31) == 0) { redv[tid >> 5] = vp; redg[tid >> 5] = gp; }
    __syncthreads();
    if (tid == 0) {
        float v_prior = softplusf(redv[0] + redv[1] + kp_b2[0]);
        float Kt = sigmoidf_(redg[0] + redg[1] + kg_b2[0]);
        float macc = km_b2[0];
#pragma unroll
        for (int k = 0; k < 32; k++)
            macc = fmaf(siluf(fmaf(z, km_w1[k], km_b1[k])), km_w2[k], macc);
        float m_t = softplusf(macc);
        float vpost = v_prior + Kt * (m_t - kW[0] * v_prior);
        vpost = fminf(fmaxf(vpost, 1e-6f), 10.f);
        out[r] = vpost;
    }
}

// ---------------- 8) per-batch softmax reductions ---------------------------
__global__ void reduce_k(float* __restrict__ out) {
    __shared__ float sa[256], sb[256];
    int b = blockIdx.x;
    int tid = threadIdx.x;                 // 256 threads, 2 elems each
    const float* v = out + (size_t)b * TT;
    float v0 = v[tid], v1 = v[tid + 256];

    sa[tid] = fmaxf(v0, v1);
    sb[tid] = fminf(v0, v1);
    __syncthreads();
    for (int s = 128; s > 0; s >>= 1) {
        if (tid < s) {
            sa[tid] = fmaxf(sa[tid], sa[tid + s]);
            sb[tid] = fminf(sb[tid], sb[tid + s]);
        }
        __syncthreads();
    }
    float mx = sa[0], mn = sb[0];
    __syncthreads();

    float e0 = __expf(v0 - mx), e1 = __expf(v1 - mx);
    sa[tid] = e0 + e1;
    sb[tid] = e0 * v0 + e1 * v1;
    __syncthreads();
    for (int s = 128; s > 0; s >>= 1) {
        if (tid < s) { sa[tid] += sa[tid + s]; sb[tid] += sb[tid + s]; }
        __syncthreads();
    }
    float spden = sa[0], spnum = sb[0];
    __syncthreads();

    float f0 = __expf(mn - v0), f1 = __expf(mn - v1);
    sa[tid] = f0 + f1;
    sb[tid] = f0 * v0 + f1 * v1;
    __syncthreads();
    for (int s = 128; s > 0; s >>= 1) {
        if (tid < s) { sa[tid] += sa[tid + s]; sb[tid] += sb[tid + s]; }
        __syncthreads();
    }
    if (tid == 0) {
        out[ROWS + b] = spnum / spden;
        out[ROWS + BB + b] = sb[0] / sa[0];
    }
}

// ---------------- launcher ---------------------------------------------------
extern "C" void kernel_launch(void* const* d_in, const int* in_sizes, int n_in,
                              void* d_out, int out_size) {
    const float* tokens   = (const float*)d_in[0];
    const float* z_t      = (const float*)d_in[1];
    const float* norm_w   = (const float*)d_in[2];
    const float* in_w     = (const float*)d_in[3];
    const float* in_b     = (const float*)d_in[4];
    const float* conv_w   = (const float*)d_in[5];
    const float* conv_b   = (const float*)d_in[6];
    const float* dt_bias  = (const float*)d_in[7];
    const float* A_log    = (const float*)d_in[8];
    const float* Dp       = (const float*)d_in[9];
    const float* gnorm_w  = (const float*)d_in[10];
    const float* out_w    = (const float*)d_in[11];
    const float* out_b    = (const float*)d_in[12];
    const float* kp_w1    = (const float*)d_in[13];
    const float* kp_b1    = (const float*)d_in[14];
    const float* kp_w2    = (const float*)d_in[15];
    const float* kp_b2    = (const float*)d_in[16];
    const float* km_w1    = (const float*)d_in[17];
    const float* km_b1    = (const float*)d_in[18];
    const float* km_w2    = (const float*)d_in[19];
    const float* km_b2    = (const float*)d_in[20];
    const float* kg_w1    = (const float*)d_in[21];
    const float* kg_b1    = (const float*)d_in[22];
    const float* kg_w2    = (const float*)d_in[23];
    const float* kg_b2    = (const float*)d_in[24];
    const float* kW       = (const float*)d_in[25];
    const float* init_st  = (const float*)d_in[26];
    float* out = (float*)d_out;

    float *xn, *zx, *xbc, *y, *tout, *hloc, *hstart, *cum;
    cudaGetSymbolAddress((void**)&xn,     g_xn);
    cudaGetSymbolAddress((void**)&zx,     g_zx);
    cudaGetSymbolAddress((void**)&xbc,    g_xbc);
    cudaGetSymbolAddress((void**)&y,      g_y);
    cudaGetSymbolAddress((void**)&tout,   g_tout);
    cudaGetSymbolAddress((void**)&hloc,   g_hloc);
    cudaGetSymbolAddress((void**)&hstart, g_hstart);
    cudaGetSymbolAddress((void**)&cum,    g_cum);

    // 1) rmsnorm
    rmsnorm_k<<<ROWS, 64>>>(tokens, norm_w, xn);
    // 2) in-proj GEMM (32768x256 @ 256x1064)
    gemm128_k<<<dim3((PROJ + 127) / 128, ROWS / 128), 256>>>(xn, in_w, in_b, nullptr, zx,
                                                             ROWS, HID, PROJ);
    // 3) conv + silu
    {
        int total = ROWS * CCH;
        conv_k<<<(total + 255) / 256, 256>>>(zx, conv_w, conv_b, xbc);
    }
    // 4) chunked scan
    scanA_k<<<dim3(NHH, BB, NC), 64>>>(xbc, zx, dt_bias, A_log, Dp, y, hloc, cum);
    scanB_k<<<dim3(NHH, BB), 64>>>(hloc, cum, hstart);
    scanC_k<<<dim3(NHH, BB, NC - 1), 64>>>(xbc, hstart, cum, y);
    // 5) gate + rmsnorm
    gatenorm_k<<<ROWS, 128>>>(y, zx, gnorm_w);
    // 6) out-proj GEMM + residual (32768x512 @ 512x256)
    gemm128_k<<<dim3(HID / 128, ROWS / 128), 256>>>(y, out_w, out_b, tokens, tout,
                                                    ROWS, DI, HID);
    // 7) Kalman head -> v_post into out[0:32768]
    kalman_k<<<ROWS, 64>>>(tout, z_t, init_st,
                           kp_w1, kp_b1, kp_w2, kp_b2,
                           km_w1, km_b1, km_w2, km_b2,
                           kg_w1, kg_b1, kg_w2, kg_b2, kW, out);
    // 8) per-batch reductions
    reduce_k<<<BB, 256>>>(out);
}

// round 6
// speedup vs baseline: 1.8194x; 1.3928x over previous
#include <cuda_runtime.h>
#include <cuda_bf16.h>
#include <cstdint>

#define BB    64
#define TT    512
#define HID   256
#define DI    512
#define DS    16
#define NHH   8
#define HD    64
#define DCONV 4
#define CCH   544    // DI + 2*DS
#define PROJ  1064   // 2*DI + 2*DS + NH
#define ROWS  (BB*TT) // 32768
#define NC    8
#define LC    64     // TT/NC
#define NT1   1152   // PROJ padded to 9*128

// ---------------- scratch (device globals; no allocation allowed) ----------
__device__ float g_zx[ROWS * PROJ];
__device__ float g_xbc[ROWS * CCH];
__device__ float g_y[ROWS * DI];
__device__ float g_tout[ROWS * HID];
__device__ float g_hloc[BB * NHH * NC * HD * DS];
__device__ float g_hstart[BB * NHH * NC * HD * DS];
__device__ float g_cum[BB * NHH * TT];
__device__ __nv_bfloat16 g_xh[ROWS * HID];
__device__ __nv_bfloat16 g_xl[ROWS * HID];
__device__ __nv_bfloat16 g_yh[ROWS * DI];
__device__ __nv_bfloat16 g_yl[ROWS * DI];
__device__ __nv_bfloat16 g_ph[ROWS * HID];
__device__ __nv_bfloat16 g_pl[ROWS * HID];
__device__ float g_ap[ROWS * 128];
__device__ __nv_bfloat16 g_wt1h[NT1 * HID];
__device__ __nv_bfloat16 g_wt1l[NT1 * HID];
__device__ __nv_bfloat16 g_wt2h[HID * DI];
__device__ __nv_bfloat16 g_wt2l[HID * DI];
__device__ __nv_bfloat16 g_wkh[128 * HID];
__device__ __nv_bfloat16 g_wkl[128 * HID];
__device__ float g_kb[128];

// ---------------- helpers ---------------------------------------------------
__device__ __forceinline__ float siluf(float x) { return x / (1.f + __expf(-x)); }
__device__ __forceinline__ float softplusf(float x) {
    return (x > 20.f) ? x : log1pf(__expf(x));
}
__device__ __forceinline__ float sigmoidf_(float x) { return 1.f / (1.f + __expf(-x)); }
__device__ __forceinline__ float warpSum(float v) {
#pragma unroll
    for (int o = 16; o; o >>= 1) v += __shfl_xor_sync(0xffffffffu, v, o);
    return v;
}
__device__ __forceinline__ void bf16split(float v, __nv_bfloat16* h, __nv_bfloat16* l) {
    __nv_bfloat16 hi = __float2bfloat16(v);
    *h = hi;
    *l = __float2bfloat16(v - __bfloat162float(hi));
}
__device__ __forceinline__ uint32_t smem_u32(const void* p) {
    uint32_t a;
    asm("{ .reg .u64 t; cvta.to.shared.u64 t, %1; cvt.u32.u64 %0, t; }"
        : "=r"(a) : "l"(p));
    return a;
}
#define SWZ(b) ((b) ^ (((b) >> 3) & 0x70))

__device__ __forceinline__ void ldsm_x4(uint32_t* r, uint32_t addr) {
    asm volatile("ldmatrix.sync.aligned.m8n8.x4.shared.b16 {%0,%1,%2,%3}, [%4];"
                 : "=r"(r[0]), "=r"(r[1]), "=r"(r[2]), "=r"(r[3]) : "r"(addr));
}
__device__ __forceinline__ void mma16816(float* c, const uint32_t* a, const uint32_t* b) {
    asm volatile("mma.sync.aligned.m16n8k16.row.col.f32.bf16.bf16.f32 "
                 "{%0,%1,%2,%3}, {%4,%5,%6,%7}, {%8,%9}, {%0,%1,%2,%3};"
                 : "+f"(c[0]), "+f"(c[1]), "+f"(c[2]), "+f"(c[3])
                 : "r"(a[0]), "r"(a[1]), "r"(a[2]), "r"(a[3]), "r"(b[0]), "r"(b[1]));
}

// ---------------- bf16 split GEMM via mma.sync ------------------------------
// C[M,N] = A@W^T + bias (+res). Ah/Al: [M,K] bf16 row-major.
// Bh/Bl: [NT,K] bf16 row-major (W transposed, zero-padded). K%32==0.
// CTA tile 128x128, BK=32, 8 warps (2x4), warp tile 64x32.
__global__ __launch_bounds__(256) void gemm_mma(
    const __nv_bfloat16* __restrict__ Ah, const __nv_bfloat16* __restrict__ Al,
    const __nv_bfloat16* __restrict__ Bh, const __nv_bfloat16* __restrict__ Bl,
    const float* __restrict__ bias, const float* __restrict__ res,
    float* __restrict__ C, int K, int N)
{
    __shared__ __align__(16) uint8_t smem[4 * 8192];   // AH, AL, BH, BL tiles
    uint8_t* sAH = smem;
    uint8_t* sAL = smem + 8192;
    uint8_t* sBH = smem + 16384;
    uint8_t* sBL = smem + 24576;

    int tid = threadIdx.x;
    int wid = tid >> 5, lane = tid & 31;
    int bm = blockIdx.y * 128, bn = blockIdx.x * 128;
    int wm = (wid >> 2) * 64;        // warp m-offset (0/64)
    int wn = (wid & 3) * 32;         // warp n-offset

    // tile loader mapping: row = tid/2 (0..127), two 16B chunks per tile
    int lrow = tid >> 1;
    int lke  = (tid & 1) * 16;       // element offset 0 or 16 within 32-wide chunk
    const __nv_bfloat16* pAh = Ah + (size_t)(bm + lrow) * K + lke;
    const __nv_bfloat16* pAl = Al + (size_t)(bm + lrow) * K + lke;
    const __nv_bfloat16* pBh = Bh + (size_t)(bn + lrow) * K + lke;
    const __nv_bfloat16* pBl = Bl + (size_t)(bn + lrow) * K + lke;
    uint32_t so0 = SWZ(lrow * 64 + lke * 2);
    uint32_t so1 = SWZ(lrow * 64 + lke * 2 + 16);

    float acc[4][4][4];
#pragma unroll
    for (int i = 0; i < 4; i++)
#pragma unroll
        for (int j = 0; j < 4; j++)
#pragma unroll
            for (int q = 0; q < 4; q++) acc[i][j][q] = 0.f;

    // prefetch chunk 0
    uint4 vAh0 = *(const uint4*)(pAh);     uint4 vAh1 = *(const uint4*)(pAh + 8);
    uint4 vAl0 = *(const uint4*)(pAl);     uint4 vAl1 = *(const uint4*)(pAl + 8);
    uint4 vBh0 = *(const uint4*)(pBh);     uint4 vBh1 = *(const uint4*)(pBh + 8);
    uint4 vBl0 = *(const uint4*)(pBl);     uint4 vBl1 = *(const uint4*)(pBl + 8);

    // ldmatrix lane addressing (byte offsets within tile)
    int aRow = lane & 15;
    int aKb  = (lane >> 4) << 4;                 // 0 or 16 bytes
    int bRow = ((lane >> 4) << 3) + (lane & 7);
    int bKb  = ((lane >> 3) & 1) << 4;

    uint32_t sbAH = smem_u32(sAH), sbAL = smem_u32(sAL);
    uint32_t sbBH = smem_u32(sBH), sbBL = smem_u32(sBL);

    const int KC = K >> 5;
    for (int c = 0; c < KC; c++) {
        // commit prefetched chunk
        *(uint4*)(sAH + so0) = vAh0;  *(uint4*)(sAH + so1) = vAh1;
        *(uint4*)(sAL + so0) = vAl0;  *(uint4*)(sAL + so1) = vAl1;
        *(uint4*)(sBH + so0) = vBh0;  *(uint4*)(sBH + so1) = vBh1;
        *(uint4*)(sBL + so0) = vBl0;  *(uint4*)(sBL + so1) = vBl1;
        __syncthreads();

        // prefetch next chunk
        if (c + 1 < KC) {
            int e = (c + 1) * 32;
            vAh0 = *(const uint4*)(pAh + e);  vAh1 = *(const uint4*)(pAh + e + 8);
            vAl0 = *(const uint4*)(pAl + e);  vAl1 = *(const uint4*)(pAl + e + 8);
            vBh0 = *(const uint4*)(pBh + e);  vBh1 = *(const uint4*)(pBh + e + 8);
            vBl0 = *(const uint4*)(pBl + e);  vBl1 = *(const uint4*)(pBl + e + 8);
        }

#pragma unroll
        for (int ks = 0; ks < 2; ks++) {
            int kb = ks * 32;
            uint32_t ah[4][4], al[4][4], bh[2][4], bl[2][4];
#pragma unroll
            for (int mt = 0; mt < 4; mt++) {
                uint32_t off = SWZ((uint32_t)(wm + mt * 16 + aRow) * 64 + kb + aKb);
                ldsm_x4(ah[mt], sbAH + off);
                ldsm_x4(al[mt], sbAL + off);
            }
#pragma unroll
            for (int np = 0; np < 2; np++) {
                uint32_t off = SWZ((uint32_t)(wn + np * 16 + bRow) * 64 + kb + bKb);
                ldsm_x4(bh[np], sbBH + off);
                ldsm_x4(bl[np], sbBL + off);
            }
#pragma unroll
            for (int mt = 0; mt < 4; mt++) {
#pragma unroll
                for (int nt = 0; nt < 4; nt++) {
                    const uint32_t* pbh = &bh[nt >> 1][(nt & 1) * 2];
                    const uint32_t* pbl = &bl[nt >> 1][(nt & 1) * 2];
                    mma16816(acc[mt][nt], ah[mt], pbh);
                    mma16816(acc[mt][nt], ah[mt], pbl);
                    mma16816(acc[mt][nt], al[mt], pbh);
                }
            }
        }
        __syncthreads();
    }

    // epilogue
    int mrow0 = bm + wm + (lane >> 2);
    int ncol0 = bn + wn + (lane & 3) * 2;
#pragma unroll
    for (int mt = 0; mt < 4; mt++) {
#pragma unroll
        for (int half = 0; half < 2; half++) {
            int m = mrow0 + mt * 16 + half * 8;
            float* crow = C + (size_t)m * N;
            const float* rrow = res ? res + (size_t)m * N : nullptr;
#pragma unroll
            for (int nt = 0; nt < 4; nt++) {
                int n = ncol0 + nt * 8;
                if (n + 1 < N) {
                    float v0 = acc[mt][nt][half * 2 + 0] + bias[n];
                    float v1 = acc[mt][nt][half * 2 + 1] + bias[n + 1];
                    if (res) { v0 += rrow[n]; v1 += rrow[n + 1]; }
                    crow[n] = v0; crow[n + 1] = v1;
                } else if (n < N) {
                    float v0 = acc[mt][nt][half * 2 + 0] + bias[n];
                    if (res) v0 += rrow[n];
                    crow[n] = v0;
                }
            }
        }
    }
}

// ---------------- 1) rmsnorm of tokens -> bf16 hi/lo ------------------------
__global__ void rmsnorm_cvt_k(const float* __restrict__ x, const float* __restrict__ w,
                              __nv_bfloat16* __restrict__ oh, __nv_bfloat16* __restrict__ ol) {
    int r = blockIdx.x;
    int tid = threadIdx.x;                 // 64 threads, 4 elems each
    float4 v = ((const float4*)(x + (size_t)r * HID))[tid];
    float ss = v.x*v.x + v.y*v.y + v.z*v.z + v.w*v.w;
    ss = warpSum(ss);
    __shared__ float red[2];
    if ((tid & 31) == 0) red[tid >> 5] = ss;
    __syncthreads();
    float sc = rsqrtf((red[0] + red[1]) / HID + 1e-5f);
    float4 wv = ((const float4*)w)[tid];
    float o[4] = {v.x*sc*wv.x, v.y*sc*wv.y, v.z*sc*wv.z, v.w*sc*wv.w};
    __nv_bfloat16 hh[4], ll[4];
#pragma unroll
    for (int i = 0; i < 4; i++) bf16split(o[i], &hh[i], &ll[i]);
    *(uint2*)(oh + (size_t)r * HID + tid * 4) = *(uint2*)hh;
    *(uint2*)(ol + (size_t)r * HID + tid * 4) = *(uint2*)ll;
}

// ---------------- weight transposes + split ---------------------------------
__global__ void wtrans1_k(const float* __restrict__ in_w,
                          __nv_bfloat16* __restrict__ h, __nv_bfloat16* __restrict__ l) {
    int idx = blockIdx.x * blockDim.x + threadIdx.x;   // NT1*HID
    if (idx >= NT1 * HID) return;
    int n = idx / HID, k = idx % HID;
    float v = (n < PROJ) ? in_w[(size_t)k * PROJ + n] : 0.f;
    bf16split(v, &h[idx], &l[idx]);
}
__global__ void wtrans2_k(const float* __restrict__ out_w,
                          __nv_bfloat16* __restrict__ h, __nv_bfloat16* __restrict__ l) {
    int idx = blockIdx.x * blockDim.x + threadIdx.x;   // HID*DI
    if (idx >= HID * DI) return;
    int n = idx / DI, k = idx % DI;
    float v = out_w[(size_t)k * HID + n];
    bf16split(v, &h[idx], &l[idx]);
}
__global__ void wktrans_k(const float* __restrict__ kp_w1, const float* __restrict__ kg_w1,
                          const float* __restrict__ kp_b1, const float* __restrict__ kg_b1,
                          __nv_bfloat16* __restrict__ h, __nv_bfloat16* __restrict__ l,
                          float* __restrict__ kb) {
    int idx = blockIdx.x * blockDim.x + threadIdx.x;   // 128*HID
    if (idx >= 128 * HID) return;
    int n = idx / HID, k = idx % HID;
    float v = (n < 64) ? kp_w1[(size_t)k * 64 + n] : kg_w1[(size_t)k * 64 + (n - 64)];
    bf16split(v, &h[idx], &l[idx]);
    if (idx < 128) kb[idx] = (idx < 64) ? kp_b1[idx] : kg_b1[idx - 64];
}

// ---------------- 3) causal depthwise conv + silu ---------------------------
__global__ void conv_k(const float* __restrict__ zx, const float* __restrict__ cw,
                       const float* __restrict__ cb, float* __restrict__ out) {
    int idx = blockIdx.x * blockDim.x + threadIdx.x;
    int total = ROWS * CCH;
    if (idx >= total) return;
    int c = idx % CCH;
    int row = idx / CCH;
    int t = row % TT;
    int b = row / TT;
    float acc = cb[c];
#pragma unroll
    for (int k = 0; k < DCONV; k++) {
        int tt = t - (DCONV - 1) + k;
        if (tt >= 0)
            acc = fmaf(zx[((size_t)(b * TT + tt)) * PROJ + DI + c], cw[k * CCH + c], acc);
    }
    out[(size_t)row * CCH + c] = siluf(acc);
}

// ---------------- 4a) chunked scan: local pass ------------------------------
__global__ __launch_bounds__(64) void scanA_k(
    const float* __restrict__ xbc, const float* __restrict__ zx,
    const float* __restrict__ dt_bias, const float* __restrict__ A_log,
    const float* __restrict__ Dp, float* __restrict__ y,
    float* __restrict__ hloc, float* __restrict__ cum)
{
    __shared__ float sBC[LC][32];
    __shared__ float sdt[LC];
    int h = blockIdx.x, b = blockIdx.y, c = blockIdx.z;
    int d = threadIdx.x;
    int t0 = c * LC;
    size_t rowbase = (size_t)(b * TT + t0);

    for (int i = d; i < LC * 32; i += 64) {
        int t = i >> 5, j = i & 31;
        sBC[t][j] = xbc[(rowbase + t) * CCH + DI + j];
    }
    float dtb = dt_bias[h];
    for (int i = d; i < LC; i += 64)
        sdt[i] = softplusf(zx[(rowbase + i) * PROJ + 2 * DI + 2 * DS + h] + dtb);
    __syncthreads();

    float A = -__expf(A_log[h]);
    float Dh = Dp[h];
    float hr[DS];
#pragma unroll
    for (int s = 0; s < DS; s++) hr[s] = 0.f;
    float cm = 1.f;

    const float* xp = xbc + rowbase * CCH + h * HD + d;
    float* yp = y + rowbase * DI + h * HD + d;
    float* cmp = cum + ((size_t)(b * NHH + h)) * TT + t0;

    for (int t = 0; t < LC; t++) {
        float x = xp[(size_t)t * CCH];
        float dtsp = sdt[t];
        float dA = __expf(dtsp * A);
        cm *= dA;
        if (d == 0) cmp[t] = cm;
        float dtx = dtsp * x;
        float yv = Dh * x;
        float Bv[16], Cv[16];
        *(float4*)&Bv[0]  = *(const float4*)&sBC[t][0];
        *(float4*)&Bv[4]  = *(const float4*)&sBC[t][4];
        *(float4*)&Bv[8]  = *(const float4*)&sBC[t][8];
        *(float4*)&Bv[12] = *(const float4*)&sBC[t][12];
        *(float4*)&Cv[0]  = *(const float4*)&sBC[t][16];
        *(float4*)&Cv[4]  = *(const float4*)&sBC[t][20];
        *(float4*)&Cv[8]  = *(const float4*)&sBC[t][24];
        *(float4*)&Cv[12] = *(const float4*)&sBC[t][28];
#pragma unroll
        for (int s = 0; s < DS; s++) {
            hr[s] = fmaf(hr[s], dA, dtx * Bv[s]);
            yv = fmaf(hr[s], Cv[s], yv);
        }
        yp[(size_t)t * DI] = yv;
    }

    float* hl = hloc + ((size_t)((b * NHH + h) * NC + c)) * (DS * HD);
#pragma unroll
    for (int s = 0; s < DS; s++) hl[s * HD + d] = hr[s];
}

// ---------------- 4b) chunked scan: chain chunk states ----------------------
__global__ __launch_bounds__(64) void scanB_k(const float* __restrict__ hloc,
                                              const float* __restrict__ cum,
                                              float* __restrict__ hstart)
{
    int h = blockIdx.x, b = blockIdx.y, d = threadIdx.x;
    size_t base = (size_t)(b * NHH + h);
    float hs[DS];
#pragma unroll
    for (int s = 0; s < DS; s++) hs[s] = 0.f;
    for (int c = 0; c < NC; c++) {
        float* hsp = hstart + (base * NC + c) * (DS * HD);
#pragma unroll
        for (int s = 0; s < DS; s++) hsp[s * HD + d] = hs[s];
        float P = cum[base * TT + c * LC + LC - 1];
        const float* hl = hloc + (base * NC + c) * (DS * HD);
#pragma unroll
        for (int s = 0; s < DS; s++) hs[s] = fmaf(hs[s], P, hl[s * HD + d]);
    }
}

// ---------------- 4c) chunked scan: correction ------------------------------
__global__ __launch_bounds__(64) void scanC_k(const float* __restrict__ xbc,
                                              const float* __restrict__ hstart,
                                              const float* __restrict__ cum,
                                              float* __restrict__ y)
{
    __shared__ float sC[LC][16];
    __shared__ float scm[LC];
    int h = blockIdx.x, b = blockIdx.y, c = blockIdx.z + 1;
    int d = threadIdx.x;
    int t0 = c * LC;
    size_t rowbase = (size_t)(b * TT + t0);
    size_t base = (size_t)(b * NHH + h);

    for (int i = d; i < LC * 16; i += 64) {
        int t = i >> 4, j = i & 15;
        sC[t][j] = xbc[(rowbase + t) * CCH + DI + DS + j];
    }
    for (int i = d; i < LC; i += 64) scm[i] = cum[base * TT + t0 + i];

    float hs[DS];
    const float* hsp = hstart + (base * NC + c) * (DS * HD);
#pragma unroll
    for (int s = 0; s < DS; s++) hs[s] = hsp[s * HD + d];
    __syncthreads();

    float* yp = y + rowbase * DI + h * HD + d;
    for (int t = 0; t < LC; t++) {
        float Cv[16];
        *(float4*)&Cv[0]  = *(const float4*)&sC[t][0];
        *(float4*)&Cv[4]  = *(const float4*)&sC[t][4];
        *(float4*)&Cv[8]  = *(const float4*)&sC[t][8];
        *(float4*)&Cv[12] = *(const float4*)&sC[t][12];
        float acc = 0.f;
#pragma unroll
        for (int s = 0; s < DS; s++) acc = fmaf(hs[s], Cv[s], acc);
        yp[(size_t)t * DI] += acc * scm[t];
    }
}

// ---------------- 5) gate + rmsnorm -> bf16 hi/lo ---------------------------
__global__ void gatenorm_cvt_k(const float* __restrict__ y, const float* __restrict__ zx,
                               const float* __restrict__ gw,
                               __nv_bfloat16* __restrict__ oh, __nv_bfloat16* __restrict__ ol) {
    int r = blockIdx.x;
    int tid = threadIdx.x;                 // 128 threads x 4
    float4 yv = ((const float4*)(y + (size_t)r * DI))[tid];
    float4 zv = ((const float4*)(zx + (size_t)r * PROJ))[tid];
    float4 g;
    g.x = yv.x * siluf(zv.x); g.y = yv.y * siluf(zv.y);
    g.z = yv.z * siluf(zv.z); g.w = yv.w * siluf(zv.w);
    float ss = g.x*g.x + g.y*g.y + g.z*g.z + g.w*g.w;
    ss = warpSum(ss);
    __shared__ float red[4];
    if ((tid & 31) == 0) red[tid >> 5] = ss;
    __syncthreads();
    float sc = rsqrtf((red[0] + red[1] + red[2] + red[3]) / DI + 1e-5f);
    float4 wv = ((const float4*)gw)[tid];
    float o[4] = {g.x*sc*wv.x, g.y*sc*wv.y, g.z*sc*wv.z, g.w*sc*wv.w};
    __nv_bfloat16 hh[4], ll[4];
#pragma unroll
    for (int i = 0; i < 4; i++) bf16split(o[i], &hh[i], &ll[i]);
    *(uint2*)(oh + (size_t)r * DI + tid * 4) = *(uint2*)hh;
    *(uint2*)(ol + (size_t)r * DI + tid * 4) = *(uint2*)ll;
}

// ---------------- 7a) shifted prior rows -> bf16 hi/lo ----------------------
__global__ void cvt_prev_k(const float* __restrict__ tout, const float* __restrict__ init_state,
                           __nv_bfloat16* __restrict__ oh, __nv_bfloat16* __restrict__ ol) {
    int r = blockIdx.x;
    int tid = threadIdx.x;                 // 64 threads x 4
    const float* src = ((r % TT) == 0) ? init_state : (tout + (size_t)(r - 1) * HID);
    float4 v = ((const float4*)src)[tid];
    float o[4] = {v.x, v.y, v.z, v.w};
    __nv_bfloat16 hh[4], ll[4];
#pragma unroll
    for (int i = 0; i < 4; i++) bf16split(o[i], &hh[i], &ll[i]);
    *(uint2*)(oh + (size_t)r * HID + tid * 4) = *(uint2*)hh;
    *(uint2*)(ol + (size_t)r * HID + tid * 4) = *(uint2*)ll;
}

// ---------------- 7b) Kalman finish -----------------------------------------
__global__ __launch_bounds__(64) void kalman_fin_k(
    const float* __restrict__ AP, const float* __restrict__ z_t,
    const float* __restrict__ kg_w1,
    const float* __restrict__ kp_w2, const float* __restrict__ kp_b2,
    const float* __restrict__ km_w1, const float* __restrict__ km_b1,
    const float* __restrict__ km_w2, const float* __restrict__ km_b2,
    const float* __restrict__ kg_w2, const float* __restrict__ kg_b2,
    const float* __restrict__ kW, float* __restrict__ out)
{
    __shared__ float redv[2], redg[2];
    int r = blockIdx.x;
    int tid = threadIdx.x;                 // 64 threads
    float z = z_t[r];
    float ap = AP[(size_t)r * 128 + tid];
    float ag = AP[(size_t)r * 128 + 64 + tid];
    ag = fmaf(z, kg_w1[HID * 64 + tid], ag);
    float vp = siluf(ap) * kp_w2[tid];
    float gp = siluf(ag) * kg_w2[tid];
    vp = warpSum(vp);
    gp = warpSum(gp);
    if ((tid & 31) == 0) { redv[tid >> 5] = vp; redg[tid >> 5] = gp; }
    __syncthreads();
    if (tid == 0) {
        float v_prior = softplusf(redv[0] + redv[1] + kp_b2[0]);
        float Kt = sigmoidf_(redg[0] + redg[1] + kg_b2[0]);
        float macc = km_b2[0];
#pragma unroll
        for (int k = 0; k < 32; k++)
            macc = fmaf(siluf(fmaf(z, km_w1[k], km_b1[k])), km_w2[k], macc);
        float m_t = softplusf(macc);
        float vpost = v_prior + Kt * (m_t - kW[0] * v_prior);
        vpost = fminf(fmaxf(vpost, 1e-6f), 10.f);
        out[r] = vpost;
    }
}

// ---------------- 8) per-batch softmax reductions ---------------------------
__global__ void reduce_k(float* __restrict__ out) {
    __shared__ float sa[256], sb[256];
    int b = blockIdx.x;
    int tid = threadIdx.x;
    const float* v = out + (size_t)b * TT;
    float v0 = v[tid], v1 = v[tid + 256];

    sa[tid] = fmaxf(v0, v1);
    sb[tid] = fminf(v0, v1);
    __syncthreads();
    for (int s = 128; s > 0; s >>= 1) {
        if (tid < s) {
            sa[tid] = fmaxf(sa[tid], sa[tid + s]);
            sb[tid] = fminf(sb[tid], sb[tid + s]);
        }
        __syncthreads();
    }
    float mx = sa[0], mn = sb[0];
    __syncthreads();

    float e0 = __expf(v0 - mx), e1 = __expf(v1 - mx);
    sa[tid] = e0 + e1;
    sb[tid] = e0 * v0 + e1 * v1;
    __syncthreads();
    for (int s = 128; s > 0; s >>= 1) {
        if (tid < s) { sa[tid] += sa[tid + s]; sb[tid] += sb[tid + s]; }
        __syncthreads();
    }
    float spden = sa[0], spnum = sb[0];
    __syncthreads();

    float f0 = __expf(mn - v0), f1 = __expf(mn - v1);
    sa[tid] = f0 + f1;
    sb[tid] = f0 * v0 + f1 * v1;
    __syncthreads();
    for (int s = 128; s > 0; s >>= 1) {
        if (tid < s) { sa[tid] += sa[tid + s]; sb[tid] += sb[tid + s]; }
        __syncthreads();
    }
    if (tid == 0) {
        out[ROWS + b] = spnum / spden;
        out[ROWS + BB + b] = sb[0] / sa[0];
    }
}

// ---------------- launcher ---------------------------------------------------
extern "C" void kernel_launch(void* const* d_in, const int* in_sizes, int n_in,
                              void* d_out, int out_size) {
    const float* tokens   = (const float*)d_in[0];
    const float* z_t      = (const float*)d_in[1];
    const float* norm_w   = (const float*)d_in[2];
    const float* in_w     = (const float*)d_in[3];
    const float* in_b     = (const float*)d_in[4];
    const float* conv_w   = (const float*)d_in[5];
    const float* conv_b   = (const float*)d_in[6];
    const float* dt_bias  = (const float*)d_in[7];
    const float* A_log    = (const float*)d_in[8];
    const float* Dp       = (const float*)d_in[9];
    const float* gnorm_w  = (const float*)d_in[10];
    const float* out_w    = (const float*)d_in[11];
    const float* out_b    = (const float*)d_in[12];
    const float* kp_w1    = (const float*)d_in[13];
    const float* kp_b1    = (const float*)d_in[14];
    const float* kp_w2    = (const float*)d_in[15];
    const float* kp_b2    = (const float*)d_in[16];
    const float* km_w1    = (const float*)d_in[17];
    const float* km_b1    = (const float*)d_in[18];
    const float* km_w2    = (const float*)d_in[19];
    const float* km_b2    = (const float*)d_in[20];
    const float* kg_w1    = (const float*)d_in[21];
    const float* kg_b1    = (const float*)d_in[22];
    const float* kg_w2    = (const float*)d_in[23];
    const float* kg_b2    = (const float*)d_in[24];
    const float* kW       = (const float*)d_in[25];
    const float* init_st  = (const float*)d_in[26];
    float* out = (float*)d_out;

    float *zx, *xbc, *y, *tout, *hloc, *hstart, *cum, *ap, *kb;
    __nv_bfloat16 *xh, *xl, *yh, *yl, *ph, *pl, *wt1h, *wt1l, *wt2h, *wt2l, *wkh, *wkl;
    cudaGetSymbolAddress((void**)&zx,     g_zx);
    cudaGetSymbolAddress((void**)&xbc,    g_xbc);
    cudaGetSymbolAddress((void**)&y,      g_y);
    cudaGetSymbolAddress((void**)&tout,   g_tout);
    cudaGetSymbolAddress((void**)&hloc,   g_hloc);
    cudaGetSymbolAddress((void**)&hstart, g_hstart);
    cudaGetSymbolAddress((void**)&cum,    g_cum);
    cudaGetSymbolAddress((void**)&ap,     g_ap);
    cudaGetSymbolAddress((void**)&kb,     g_kb);
    cudaGetSymbolAddress((void**)&xh,     g_xh);
    cudaGetSymbolAddress((void**)&xl,     g_xl);
    cudaGetSymbolAddress((void**)&yh,     g_yh);
    cudaGetSymbolAddress((void**)&yl,     g_yl);
    cudaGetSymbolAddress((void**)&ph,     g_ph);
    cudaGetSymbolAddress((void**)&pl,     g_pl);
    cudaGetSymbolAddress((void**)&wt1h,   g_wt1h);
    cudaGetSymbolAddress((void**)&wt1l,   g_wt1l);
    cudaGetSymbolAddress((void**)&wt2h,   g_wt2h);
    cudaGetSymbolAddress((void**)&wt2l,   g_wt2l);
    cudaGetSymbolAddress((void**)&wkh,    g_wkh);
    cudaGetSymbolAddress((void**)&wkl,    g_wkl);

    // weight prep (small)
    wtrans1_k<<<(NT1 * HID + 255) / 256, 256>>>(in_w, wt1h, wt1l);
    wtrans2_k<<<(HID * DI + 255) / 256, 256>>>(out_w, wt2h, wt2l);
    wktrans_k<<<(128 * HID + 255) / 256, 256>>>(kp_w1, kg_w1, kp_b1, kg_b1, wkh, wkl, kb);

    // 1) rmsnorm -> bf16 split
    rmsnorm_cvt_k<<<ROWS, 64>>>(tokens, norm_w, xh, xl);
    // 2) in-proj GEMM (mma): 32768x256 @ 256x1064
    gemm_mma<<<dim3(NT1 / 128, ROWS / 128), 256>>>(xh, xl, wt1h, wt1l, in_b, nullptr,
                                                   zx, HID, PROJ);
    // 3) conv + silu
    conv_k<<<(ROWS * CCH + 255) / 256, 256>>>(zx, conv_w, conv_b, xbc);
    // 4) chunked scan
    scanA_k<<<dim3(NHH, BB, NC), 64>>>(xbc, zx, dt_bias, A_log, Dp, y, hloc, cum);
    scanB_k<<<dim3(NHH, BB), 64>>>(hloc, cum, hstart);
    scanC_k<<<dim3(NHH, BB, NC - 1), 64>>>(xbc, hstart, cum, y);
    // 5) gate + rmsnorm -> bf16 split
    gatenorm_cvt_k<<<ROWS, 128>>>(y, zx, gnorm_w, yh, yl);
    // 6) out-proj GEMM (mma) + residual: 32768x512 @ 512x256
    gemm_mma<<<dim3(HID / 128, ROWS / 128), 256>>>(yh, yl, wt2h, wt2l, out_b, tokens,
                                                   tout, DI, HID);
    // 7) Kalman: shift+split -> GEMM (mma) -> finish
    cvt_prev_k<<<ROWS, 64>>>(tout, init_st, ph, pl);
    gemm_mma<<<dim3(1, ROWS / 128), 256>>>(ph, pl, wkh, wkl, kb, nullptr, ap, HID, 128);
    kalman_fin_k<<<ROWS, 64>>>(ap, z_t, kg_w1,
                               kp_w2, kp_b2, km_w1, km_b1, km_w2, km_b2,
                               kg_w2, kg_b2, kW, out);
    // 8) per-batch reductions
    reduce_k<<<BB, 256>>>(out);
}

// round 8
// speedup vs baseline: 2.0164x; 1.1083x over previous
#include <cuda_runtime.h>
#include <cuda_bf16.h>
#include <cstdint>

#define BB    64
#define TT    512
#define HID   256
#define DI    512
#define DS    16
#define NHH   8
#define HD    64
#define DCONV 4
#define CCH   544    // DI + 2*DS
#define PROJ  1064   // 2*DI + 2*DS + NH
#define ROWS  (BB*TT) // 32768
#define NC    16
#define LC    32     // TT/NC
#define NT1   1152   // PROJ padded to 9*128

// ---------------- scratch (device globals; no allocation allowed) ----------
__device__ __align__(16) float g_zx[ROWS * PROJ];
__device__ __align__(16) float g_xbc[ROWS * CCH];
__device__ __align__(16) float g_y[ROWS * DI];
__device__ __align__(16) float g_hloc[BB * NHH * NC * HD * DS];
__device__ __align__(16) float g_hstart[BB * NHH * NC * HD * DS];
__device__ __align__(16) float g_cum[BB * NHH * TT];
__device__ __align__(16) __nv_bfloat16 g_xh[ROWS * HID];
__device__ __align__(16) __nv_bfloat16 g_xl[ROWS * HID];
__device__ __align__(16) __nv_bfloat16 g_yh[ROWS * DI];
__device__ __align__(16) __nv_bfloat16 g_yl[ROWS * DI];
__device__ __align__(16) __nv_bfloat16 g_ph[ROWS * HID];
__device__ __align__(16) __nv_bfloat16 g_pl[ROWS * HID];
__device__ __align__(16) float g_ap[ROWS * 128];
__device__ __align__(16) __nv_bfloat16 g_wt1h[NT1 * HID];
__device__ __align__(16) __nv_bfloat16 g_wt1l[NT1 * HID];
__device__ __align__(16) __nv_bfloat16 g_wt2h[HID * DI];
__device__ __align__(16) __nv_bfloat16 g_wt2l[HID * DI];
__device__ __align__(16) __nv_bfloat16 g_wkh[128 * HID];
__device__ __align__(16) __nv_bfloat16 g_wkl[128 * HID];
__device__ __align__(16) float g_kb[128];

// ---------------- helpers ---------------------------------------------------
__device__ __forceinline__ float siluf(float x) { return x / (1.f + __expf(-x)); }
__device__ __forceinline__ float softplusf(float x) {
    return (x > 20.f) ? x : log1pf(__expf(x));
}
__device__ __forceinline__ float sigmoidf_(float x) { return 1.f / (1.f + __expf(-x)); }
__device__ __forceinline__ float warpSum(float v) {
#pragma unroll
    for (int o = 16; o; o >>= 1) v += __shfl_xor_sync(0xffffffffu, v, o);
    return v;
}
__device__ __forceinline__ void bf16split(float v, __nv_bfloat16* h, __nv_bfloat16* l) {
    __nv_bfloat16 hi = __float2bfloat16(v);
    *h = hi;
    *l = __float2bfloat16(v - __bfloat162float(hi));
}
__device__ __forceinline__ uint32_t smem_u32(const void* p) {
    uint32_t a;
    asm("{ .reg .u64 t; cvta.to.shared.u64 t, %1; cvt.u32.u64 %0, t; }"
        : "=r"(a) : "l"(p));
    return a;
}
#define SWZ(b) ((b) ^ (((b) >> 3) & 0x70))

__device__ __forceinline__ void ldsm_x4(uint32_t* r, uint32_t addr) {
    asm volatile("ldmatrix.sync.aligned.m8n8.x4.shared.b16 {%0,%1,%2,%3}, [%4];"
                 : "=r"(r[0]), "=r"(r[1]), "=r"(r[2]), "=r"(r[3]) : "r"(addr));
}
__device__ __forceinline__ void mma16816(float* c, const uint32_t* a, const uint32_t* b) {
    asm volatile("mma.sync.aligned.m16n8k16.row.col.f32.bf16.bf16.f32 "
                 "{%0,%1,%2,%3}, {%4,%5,%6,%7}, {%8,%9}, {%0,%1,%2,%3};"
                 : "+f"(c[0]), "+f"(c[1]), "+f"(c[2]), "+f"(c[3])
                 : "r"(a[0]), "r"(a[1]), "r"(a[2]), "r"(a[3]), "r"(b[0]), "r"(b[1]));
}
#define CP16(sa, gp) \
    asm volatile("cp.async.cg.shared.global [%0], [%1], 16;" :: "r"(sa), "l"(gp))
#define CP_COMMIT() asm volatile("cp.async.commit_group;" ::: "memory")
#define CP_WAIT1() asm volatile("cp.async.wait_group 1;" ::: "memory")
#define CP_WAIT0() asm volatile("cp.async.wait_group 0;" ::: "memory")

// ---------------- bf16 split GEMM via mma.sync, cp.async 2-stage ------------
// C[M,N] = A@W^T + bias (+res). Ah/Al: [M,K] bf16 row-major.
// Bh/Bl: [NT,K] bf16 row-major (W transposed, zero-padded). K%32==0.
// CTA tile 128x128, BK=32, 8 warps (2x4), warp tile 64x32.
// If oh != nullptr (requires N==HID): additionally write bf16 hi/lo of the
// result to row m+1 (skip rows where (m+1)%TT==0).
#define GSM_STAGE 32768
__global__ __launch_bounds__(256) void gemm_mma(
    const __nv_bfloat16* __restrict__ Ah, const __nv_bfloat16* __restrict__ Al,
    const __nv_bfloat16* __restrict__ Bh, const __nv_bfloat16* __restrict__ Bl,
    const float* __restrict__ bias, const float* __restrict__ res,
    float* __restrict__ C,
    __nv_bfloat16* __restrict__ oh, __nv_bfloat16* __restrict__ ol,
    int K, int N)
{
    extern __shared__ __align__(16) uint8_t dsm[];
    uint32_t sbase = smem_u32(dsm);

    int tid = threadIdx.x;
    int wid = tid >> 5, lane = tid & 31;
    int bm = blockIdx.y * 128, bn = blockIdx.x * 128;
    int wm = (wid >> 2) * 64;        // warp m-offset (0/64)
    int wn = (wid & 3) * 32;         // warp n-offset

    // tile loader mapping: row = tid/2 (0..127), two 16B chunks per tile
    int lrow = tid >> 1;
    int lke  = (tid & 1) * 16;       // element offset 0 or 16 within 32-wide chunk
    const __nv_bfloat16* pAh = Ah + (size_t)(bm + lrow) * K + lke;
    const __nv_bfloat16* pAl = Al + (size_t)(bm + lrow) * K + lke;
    const __nv_bfloat16* pBh = Bh + (size_t)(bn + lrow) * K + lke;
    const __nv_bfloat16* pBl = Bl + (size_t)(bn + lrow) * K + lke;
    uint32_t so0 = SWZ((uint32_t)(lrow * 64 + lke * 2));
    uint32_t so1 = SWZ((uint32_t)(lrow * 64 + lke * 2 + 16));

    float acc[4][4][4];
#pragma unroll
    for (int i = 0; i < 4; i++)
#pragma unroll
        for (int j = 0; j < 4; j++)
#pragma unroll
            for (int q = 0; q < 4; q++) acc[i][j][q] = 0.f;

    // ldmatrix lane addressing (byte offsets within tile)
    int aRow = lane & 15;
    int aKb  = (lane >> 4) << 4;                 // 0 or 16 bytes
    int bRow = ((lane >> 4) << 3) + (lane & 7);
    int bKb  = ((lane >> 3) & 1) << 4;

    const int KC = K >> 5;

    // prologue: stage 0 loads
    {
        uint32_t st = sbase;
        CP16(st + so0,         pAh);      CP16(st + so1,         pAh + 8);
        CP16(st + 8192 + so0,  pAl);      CP16(st + 8192 + so1,  pAl + 8);
        CP16(st + 16384 + so0, pBh);      CP16(st + 16384 + so1, pBh + 8);
        CP16(st + 24576 + so0, pBl);      CP16(st + 24576 + so1, pBl + 8);
        CP_COMMIT();
    }

    for (int c = 0; c < KC; c++) {
        if (c + 1 < KC) {
            int e = (c + 1) * 32;
            uint32_t st = sbase + ((c + 1) & 1) * GSM_STAGE;
            CP16(st + so0,         pAh + e);   CP16(st + so1,         pAh + e + 8);
            CP16(st + 8192 + so0,  pAl + e);   CP16(st + 8192 + so1,  pAl + e + 8);
            CP16(st + 16384 + so0, pBh + e);   CP16(st + 16384 + so1, pBh + e + 8);
            CP16(st + 24576 + so0, pBl + e);   CP16(st + 24576 + so1, pBl + e + 8);
            CP_COMMIT();
            CP_WAIT1();
        } else {
            CP_WAIT0();
        }
        __syncthreads();

        uint32_t st = sbase + (c & 1) * GSM_STAGE;
        uint32_t sbAH = st, sbAL = st + 8192, sbBH = st + 16384, sbBL = st + 24576;

#pragma unroll
        for (int ks = 0; ks < 2; ks++) {
            int kb = ks * 32;
            uint32_t ah[4][4], al[4][4], bh[2][4], bl[2][4];
#pragma unroll
            for (int mt = 0; mt < 4; mt++) {
                uint32_t off = SWZ((uint32_t)(wm + mt * 16 + aRow) * 64 + kb + aKb);
                ldsm_x4(ah[mt], sbAH + off);
                ldsm_x4(al[mt], sbAL + off);
            }
#pragma unroll
            for (int np = 0; np < 2; np++) {
                uint32_t off = SWZ((uint32_t)(wn + np * 16 + bRow) * 64 + kb + bKb);
                ldsm_x4(bh[np], sbBH + off);
                ldsm_x4(bl[np], sbBL + off);
            }
#pragma unroll
            for (int mt = 0; mt < 4; mt++) {
#pragma unroll
                for (int nt = 0; nt < 4; nt++) {
                    const uint32_t* pbh = &bh[nt >> 1][(nt & 1) * 2];
                    const uint32_t* pbl = &bl[nt >> 1][(nt & 1) * 2];
                    mma16816(acc[mt][nt], ah[mt], pbh);
                    mma16816(acc[mt][nt], ah[mt], pbl);
                    mma16816(acc[mt][nt], al[mt], pbh);
                }
            }
        }
        __syncthreads();
    }

    // epilogue
    int mrow0 = bm + wm + (lane >> 2);
    int ncol0 = bn + wn + (lane & 3) * 2;
#pragma unroll
    for (int mt = 0; mt < 4; mt++) {
#pragma unroll
        for (int half = 0; half < 2; half++) {
            int m = mrow0 + mt * 16 + half * 8;
            float* crow = C ? C + (size_t)m * N : nullptr;
            const float* rrow = res ? res + (size_t)m * N : nullptr;
            int mp = m + 1;
            bool doshift = (oh != nullptr) && ((mp & (TT - 1)) != 0);
#pragma unroll
            for (int nt = 0; nt < 4; nt++) {
                int n = ncol0 + nt * 8;
                if (n + 1 < N) {
                    float v0 = acc[mt][nt][half * 2 + 0] + bias[n];
                    float v1 = acc[mt][nt][half * 2 + 1] + bias[n + 1];
                    if (res) { v0 += rrow[n]; v1 += rrow[n + 1]; }
                    if (crow) { crow[n] = v0; crow[n + 1] = v1; }
                    if (doshift) {
                        __nv_bfloat16 h0, l0, h1, l1;
                        bf16split(v0, &h0, &l0);
                        bf16split(v1, &h1, &l1);
                        __nv_bfloat162 hp, lp;
                        hp.x = h0; hp.y = h1; lp.x = l0; lp.y = l1;
                        *(__nv_bfloat162*)(oh + (size_t)mp * N + n) = hp;
                        *(__nv_bfloat162*)(ol + (size_t)mp * N + n) = lp;
                    }
                } else if (n < N) {
                    float v0 = acc[mt][nt][half * 2 + 0] + bias[n];
                    if (res) v0 += rrow[n];
                    if (crow) crow[n] = v0;
                }
            }
        }
    }
}

// ---------------- init rows (t=0) of Kalman prior from init_state -----------
__global__ void initrow_k(const float* __restrict__ init_state,
                          __nv_bfloat16* __restrict__ oh, __nv_bfloat16* __restrict__ ol) {
    int b = blockIdx.x;
    int tid = threadIdx.x;                 // 64 threads x 4
    float4 v = ((const float4*)init_state)[tid];
    float o[4] = {v.x, v.y, v.z, v.w};
    __nv_bfloat16 hh[4], ll[4];
#pragma unroll
    for (int i = 0; i < 4; i++) bf16split(o[i], &hh[i], &ll[i]);
    size_t base = (size_t)(b * TT) * HID + tid * 4;
    *(uint2*)(oh + base) = *(uint2*)hh;
    *(uint2*)(ol + base) = *(uint2*)ll;
}

// ---------------- 1) rmsnorm of tokens -> bf16 hi/lo ------------------------
__global__ void rmsnorm_cvt_k(const float* __restrict__ x, const float* __restrict__ w,
                              __nv_bfloat16* __restrict__ oh, __nv_bfloat16* __restrict__ ol) {
    int r = blockIdx.x;
    int tid = threadIdx.x;                 // 64 threads, 4 elems each
    float4 v = ((const float4*)(x + (size_t)r * HID))[tid];
    float ss = v.x*v.x + v.y*v.y + v.z*v.z + v.w*v.w;
    ss = warpSum(ss);
    __shared__ float red[2];
    if ((tid & 31) == 0) red[tid >> 5] = ss;
    __syncthreads();
    float sc = rsqrtf((red[0] + red[1]) / HID + 1e-5f);
    float4 wv = ((const float4*)w)[tid];
    float o[4] = {v.x*sc*wv.x, v.y*sc*wv.y, v.z*sc*wv.z, v.w*sc*wv.w};
    __nv_bfloat16 hh[4], ll[4];
#pragma unroll
    for (int i = 0; i < 4; i++) bf16split(o[i], &hh[i], &ll[i]);
    *(uint2*)(oh + (size_t)r * HID + tid * 4) = *(uint2*)hh;
    *(uint2*)(ol + (size_t)r * HID + tid * 4) = *(uint2*)ll;
}

// ---------------- weight transposes + split ---------------------------------
__global__ void wtrans1_k(const float* __restrict__ in_w,
                          __nv_bfloat16* __restrict__ h, __nv_bfloat16* __restrict__ l) {
    int idx = blockIdx.x * blockDim.x + threadIdx.x;   // NT1*HID
    if (idx >= NT1 * HID) return;
    int n = idx / HID, k = idx % HID;
    float v = (n < PROJ) ? in_w[(size_t)k * PROJ + n] : 0.f;
    bf16split(v, &h[idx], &l[idx]);
}
__global__ void wtrans2_k(const float* __restrict__ out_w,
                          __nv_bfloat16* __restrict__ h, __nv_bfloat16* __restrict__ l) {
    int idx = blockIdx.x * blockDim.x + threadIdx.x;   // HID*DI
    if (idx >= HID * DI) return;
    int n = idx / DI, k = idx % DI;
    float v = out_w[(size_t)k * HID + n];
    bf16split(v, &h[idx], &l[idx]);
}
__global__ void wktrans_k(const float* __restrict__ kp_w1, const float* __restrict__ kg_w1,
                          const float* __restrict__ kp_b1, const float* __restrict__ kg_b1,
                          __nv_bfloat16* __restrict__ h, __nv_bfloat16* __restrict__ l,
                          float* __restrict__ kb) {
    int idx = blockIdx.x * blockDim.x + threadIdx.x;   // 128*HID
    if (idx >= 128 * HID) return;
    int n = idx / HID, k = idx % HID;
    float v = (n < 64) ? kp_w1[(size_t)k * 64 + n] : kg_w1[(size_t)k * 64 + (n - 64)];
    bf16split(v, &h[idx], &l[idx]);
    if (idx < 128) kb[idx] = (idx < 64) ? kp_b1[idx] : kg_b1[idx - 64];
}

// ---------------- 3) causal depthwise conv + silu ---------------------------
__global__ void conv_k(const float* __restrict__ zx, const float* __restrict__ cw,
                       const float* __restrict__ cb, float* __restrict__ out) {
    int idx = blockIdx.x * blockDim.x + threadIdx.x;
    int total = ROWS * CCH;
    if (idx >= total) return;
    int c = idx % CCH;
    int row = idx / CCH;
    int t = row % TT;
    int b = row / TT;
    float acc = cb[c];
#pragma unroll
    for (int k = 0; k < DCONV; k++) {
        int tt = t - (DCONV - 1) + k;
        if (tt >= 0)
            acc = fmaf(zx[((size_t)(b * TT + tt)) * PROJ + DI + c], cw[k * CCH + c], acc);
    }
    out[(size_t)row * CCH + c] = siluf(acc);
}

// ---------------- 4a) chunked scan: local pass ------------------------------
__global__ __launch_bounds__(64) void scanA_k(
    const float* __restrict__ xbc, const float* __restrict__ zx,
    const float* __restrict__ dt_bias, const float* __restrict__ A_log,
    const float* __restrict__ Dp, float* __restrict__ y,
    float* __restrict__ hloc, float* __restrict__ cum)
{
    __shared__ float sBC[LC][32];
    __shared__ float sdt[LC];
    int h = blockIdx.x, b = blockIdx.y, c = blockIdx.z;
    int d = threadIdx.x;
    int t0 = c * LC;
    size_t rowbase = (size_t)(b * TT + t0);

    for (int i = d; i < LC * 32; i += 64) {
        int t = i >> 5, j = i & 31;
        sBC[t][j] = xbc[(rowbase + t) * CCH + DI + j];
    }
    float dtb = dt_bias[h];
    for (int i = d; i < LC; i += 64)
        sdt[i] = softplusf(zx[(rowbase + i) * PROJ + 2 * DI + 2 * DS + h] + dtb);
    __syncthreads();

    float A = -__expf(A_log[h]);
    float Dh = Dp[h];
    float hr[DS];
#pragma unroll
    for (int s = 0; s < DS; s++) hr[s] = 0.f;
    float cm = 1.f;

    const float* xp = xbc + rowbase * CCH + h * HD + d;
    float* yp = y + rowbase * DI + h * HD + d;
    float* cmp = cum + ((size_t)(b * NHH + h)) * TT + t0;

    for (int t = 0; t < LC; t++) {
        float x = xp[(size_t)t * CCH];
        float dtsp = sdt[t];
        float dA = __expf(dtsp * A);
        cm *= dA;
        if (d == 0) cmp[t] = cm;
        float dtx = dtsp * x;
        float yvp[4] = {Dh * x, 0.f, 0.f, 0.f};
        float Bv[16], Cv[16];
        *(float4*)&Bv[0]  = *(const float4*)&sBC[t][0];
        *(float4*)&Bv[4]  = *(const float4*)&sBC[t][4];
        *(float4*)&Bv[8]  = *(const float4*)&sBC[t][8];
        *(float4*)&Bv[12] = *(const float4*)&sBC[t][12];
        *(float4*)&Cv[0]  = *(const float4*)&sBC[t][16];
        *(float4*)&Cv[4]  = *(const float4*)&sBC[t][20];
        *(float4*)&Cv[8]  = *(const float4*)&sBC[t][24];
        *(float4*)&Cv[12] = *(const float4*)&sBC[t][28];
#pragma unroll
        for (int s = 0; s < DS; s++) {
            hr[s] = fmaf(hr[s], dA, dtx * Bv[s]);
            yvp[s & 3] = fmaf(hr[s], Cv[s], yvp[s & 3]);
        }
        yp[(size_t)t * DI] = (yvp[0] + yvp[1]) + (yvp[2] + yvp[3]);
    }

    float* hl = hloc + ((size_t)((b * NHH + h) * NC + c)) * (DS * HD);
#pragma unroll
    for (int s = 0; s < DS; s++) hl[s * HD + d] = hr[s];
}

// ---------------- 4b) chunked scan: chain chunk states ----------------------
__global__ __launch_bounds__(64) void scanB_k(const float* __restrict__ hloc,
                                              const float* __restrict__ cum,
                                              float* __restrict__ hstart)
{
    int h = blockIdx.x, b = blockIdx.y, d = threadIdx.x;
    size_t base = (size_t)(b * NHH + h);
    float hs[DS];
#pragma unroll
    for (int s = 0; s < DS; s++) hs[s] = 0.f;
    for (int c = 0; c < NC; c++) {
        float* hsp = hstart + (base * NC + c) * (DS * HD);
#pragma unroll
        for (int s = 0; s < DS; s++) hsp[s * HD + d] = hs[s];
        float P = cum[base * TT + c * LC + LC - 1];
        const float* hl = hloc + (base * NC + c) * (DS * HD);
#pragma unroll
        for (int s = 0; s < DS; s++) hs[s] = fmaf(hs[s], P, hl[s * HD + d]);
    }
}

// ---------------- 4c) chunked scan: correction ------------------------------
__global__ __launch_bounds__(64) void scanC_k(const float* __restrict__ xbc,
                                              const float* __restrict__ hstart,
                                              const float* __restrict__ cum,
                                              float* __restrict__ y)
{
    __shared__ float sC[LC][16];
    __shared__ float scm[LC];
    int h = blockIdx.x, b = blockIdx.y, c = blockIdx.z + 1;
    int d = threadIdx.x;
    int t0 = c * LC;
    size_t rowbase = (size_t)(b * TT + t0);
    size_t base = (size_t)(b * NHH + h);

    for (int i = d; i < LC * 16; i += 64) {
        int t = i >> 4, j = i & 15;
        sC[t][j] = xbc[(rowbase + t) * CCH + DI + DS + j];
    }
    for (int i = d; i < LC; i += 64) scm[i] = cum[base * TT + t0 + i];

    float hs[DS];
    const float* hsp = hstart + (base * NC + c) * (DS * HD);
#pragma unroll
    for (int s = 0; s < DS; s++) hs[s] = hsp[s * HD + d];
    __syncthreads();

    float* yp = y + rowbase * DI + h * HD + d;
    for (int t = 0; t < LC; t++) {
        float Cv[16];
        *(float4*)&Cv[0]  = *(const float4*)&sC[t][0];
        *(float4*)&Cv[4]  = *(const float4*)&sC[t][4];
        *(float4*)&Cv[8]  = *(const float4*)&sC[t][8];
        *(float4*)&Cv[12] = *(const float4*)&sC[t][12];
        float acc = 0.f;
#pragma unroll
        for (int s = 0; s < DS; s++) acc = fmaf(hs[s], Cv[s], acc);
        yp[(size_t)t * DI] += acc * scm[t];
    }
}

// ---------------- 5) gate + rmsnorm -> bf16 hi/lo ---------------------------
__global__ void gatenorm_cvt_k(const float* __restrict__ y, const float* __restrict__ zx,
                               const float* __restrict__ gw,
                               __nv_bfloat16* __restrict__ oh, __nv_bfloat16* __restrict__ ol) {
    int r = blockIdx.x;
    int tid = threadIdx.x;                 // 128 threads x 4
    float4 yv = ((const float4*)(y + (size_t)r * DI))[tid];
    float4 zv = ((const float4*)(zx + (size_t)r * PROJ))[tid];
    float4 g;
    g.x = yv.x * siluf(zv.x); g.y = yv.y * siluf(zv.y);
    g.z = yv.z * siluf(zv.z); g.w = yv.w * siluf(zv.w);
    float ss = g.x*g.x + g.y*g.y + g.z*g.z + g.w*g.w;
    ss = warpSum(ss);
    __shared__ float red[4];
    if ((tid & 31) == 0) red[tid >> 5] = ss;
    __syncthreads();
    float sc = rsqrtf((red[0] + red[1] + red[2] + red[3]) / DI + 1e-5f);
    float4 wv = ((const float4*)gw)[tid];
    float o[4] = {g.x*sc*wv.x, g.y*sc*wv.y, g.z*sc*wv.z, g.w*sc*wv.w};
    __nv_bfloat16 hh[4], ll[4];
#pragma unroll
    for (int i = 0; i < 4; i++) bf16split(o[i], &hh[i], &ll[i]);
    *(uint2*)(oh + (size_t)r * DI + tid * 4) = *(uint2*)hh;
    *(uint2*)(ol + (size_t)r * DI + tid * 4) = *(uint2*)ll;
}

// ---------------- 7b) Kalman finish -----------------------------------------
__global__ __launch_bounds__(64) void kalman_fin_k(
    const float* __restrict__ AP, const float* __restrict__ z_t,
    const float* __restrict__ kg_w1,
    const float* __restrict__ kp_w2, const float* __restrict__ kp_b2,
    const float* __restrict__ km_w1, const float* __restrict__ km_b1,
    const float* __restrict__ km_w2, const float* __restrict__ km_b2,
    const float* __restrict__ kg_w2, const float* __restrict__ kg_b2,
    const float* __restrict__ kW, float* __restrict__ out)
{
    __shared__ float redv[2], redg[2];
    int r = blockIdx.x;
    int tid = threadIdx.x;                 // 64 threads
    float z = z_t[r];
    float ap = AP[(size_t)r * 128 + tid];
    float ag = AP[(size_t)r * 128 + 64 + tid];
    ag = fmaf(z, kg_w1[HID * 64 + tid], ag);
    float vp = siluf(ap) * kp_w2[tid];
    float gp = siluf(ag) * kg_w2[tid];
    vp = warpSum(vp);
    gp = warpSum(gp);
    if ((tid & 31) == 0) { redv[tid >> 5] = vp; redg[tid >> 5] = gp; }
    __syncthreads();
    if (tid == 0) {
        float v_prior = softplusf(redv[0] + redv[1] + kp_b2[0]);
        float Kt = sigmoidf_(redg[0] + redg[1] + kg_b2[0]);
        float macc = km_b2[0];
#pragma unroll
        for (int k = 0; k < 32; k++)
            macc = fmaf(siluf(fmaf(z, km_w1[k], km_b1[k])), km_w2[k], macc);
        float m_t = softplusf(macc);
        float vpost = v_prior + Kt * (m_t - kW[0] * v_prior);
        vpost = fminf(fmaxf(vpost, 1e-6f), 10.f);
        out[r] = vpost;
    }
}

// ---------------- 8) per-batch softmax reductions ---------------------------
__global__ void reduce_k(float* __restrict__ out) {
    __shared__ float sa[256], sb[256];
    int b = blockIdx.x;
    int tid = threadIdx.x;
    const float* v = out + (size_t)b * TT;
    float v0 = v[tid], v1 = v[tid + 256];

    sa[tid] = fmaxf(v0, v1);
    sb[tid] = fminf(v0, v1);
    __syncthreads();
    for (int s = 128; s > 0; s >>= 1) {
        if (tid < s) {
            sa[tid] = fmaxf(sa[tid], sa[tid + s]);
            sb[tid] = fminf(sb[tid], sb[tid + s]);
        }
        __syncthreads();
    }
    float mx = sa[0], mn = sb[0];
    __syncthreads();

    float e0 = __expf(v0 - mx), e1 = __expf(v1 - mx);
    sa[tid] = e0 + e1;
    sb[tid] = e0 * v0 + e1 * v1;
    __syncthreads();
    for (int s = 128; s > 0; s >>= 1) {
        if (tid < s) { sa[tid] += sa[tid + s]; sb[tid] += sb[tid + s]; }
        __syncthreads();
    }
    float spden = sa[0], spnum = sb[0];
    __syncthreads();

    float f0 = __expf(mn - v0), f1 = __expf(mn - v1);
    sa[tid] = f0 + f1;
    sb[tid] = f0 * v0 + f1 * v1;
    __syncthreads();
    for (int s = 128; s > 0; s >>= 1) {
        if (tid < s) { sa[tid] += sa[tid + s]; sb[tid] += sb[tid + s]; }
        __syncthreads();
    }
    if (tid == 0) {
        out[ROWS + b] = spnum / spden;
        out[ROWS + BB + b] = sb[0] / sa[0];
    }
}

// ---------------- launcher ---------------------------------------------------
extern "C" void kernel_launch(void* const* d_in, const int* in_sizes, int n_in,
                              void* d_out, int out_size) {
    const float* tokens   = (const float*)d_in[0];
    const float* z_t      = (const float*)d_in[1];
    const float* norm_w   = (const float*)d_in[2];
    const float* in_w     = (const float*)d_in[3];
    const float* in_b     = (const float*)d_in[4];
    const float* conv_w   = (const float*)d_in[5];
    const float* conv_b   = (const float*)d_in[6];
    const float* dt_bias  = (const float*)d_in[7];
    const float* A_log    = (const float*)d_in[8];
    const float* Dp       = (const float*)d_in[9];
    const float* gnorm_w  = (const float*)d_in[10];
    const float* out_w    = (const float*)d_in[11];
    const float* out_b    = (const float*)d_in[12];
    const float* kp_w1    = (const float*)d_in[13];
    const float* kp_b1    = (const float*)d_in[14];
    const float* kp_w2    = (const float*)d_in[15];
    const float* kp_b2    = (const float*)d_in[16];
    const float* km_w1    = (const float*)d_in[17];
    const float* km_b1    = (const float*)d_in[18];
    const float* km_w2    = (const float*)d_in[19];
    const float* km_b2    = (const float*)d_in[20];
    const float* kg_w1    = (const float*)d_in[21];
    const float* kg_b1    = (const float*)d_in[22];
    const float* kg_w2    = (const float*)d_in[23];
    const float* kg_b2    = (const float*)d_in[24];
    const float* kW       = (const float*)d_in[25];
    const float* init_st  = (const float*)d_in[26];
    float* out = (float*)d_out;

    float *zx, *xbc, *y, *hloc, *hstart, *cum, *ap, *kb;
    __nv_bfloat16 *xh, *xl, *yh, *yl, *ph, *pl, *wt1h, *wt1l, *wt2h, *wt2l, *wkh, *wkl;
    cudaGetSymbolAddress((void**)&zx,     g_zx);
    cudaGetSymbolAddress((void**)&xbc,    g_xbc);
    cudaGetSymbolAddress((void**)&y,      g_y);
    cudaGetSymbolAddress((void**)&hloc,   g_hloc);
    cudaGetSymbolAddress((void**)&hstart, g_hstart);
    cudaGetSymbolAddress((void**)&cum,    g_cum);
    cudaGetSymbolAddress((void**)&ap,     g_ap);
    cudaGetSymbolAddress((void**)&kb,     g_kb);
    cudaGetSymbolAddress((void**)&xh,     g_xh);
    cudaGetSymbolAddress((void**)&xl,     g_xl);
    cudaGetSymbolAddress((void**)&yh,     g_yh);
    cudaGetSymbolAddress((void**)&yl,     g_yl);
    cudaGetSymbolAddress((void**)&ph,     g_ph);
    cudaGetSymbolAddress((void**)&pl,     g_pl);
    cudaGetSymbolAddress((void**)&wt1h,   g_wt1h);
    cudaGetSymbolAddress((void**)&wt1l,   g_wt1l);
    cudaGetSymbolAddress((void**)&wt2h,   g_wt2h);
    cudaGetSymbolAddress((void**)&wt2l,   g_wt2l);
    cudaGetSymbolAddress((void**)&wkh,    g_wkh);
    cudaGetSymbolAddress((void**)&wkl,    g_wkl);

    cudaFuncSetAttribute(gemm_mma, cudaFuncAttributeMaxDynamicSharedMemorySize,
                         2 * GSM_STAGE);

    // weight prep (small)
    wtrans1_k<<<(NT1 * HID + 255) / 256, 256>>>(in_w, wt1h, wt1l);
    wtrans2_k<<<(HID * DI + 255) / 256, 256>>>(out_w, wt2h, wt2l);
    wktrans_k<<<(128 * HID + 255) / 256, 256>>>(kp_w1, kg_w1, kp_b1, kg_b1, wkh, wkl, kb);
    initrow_k<<<BB, 64>>>(init_st, ph, pl);

    // 1) rmsnorm -> bf16 split
    rmsnorm_cvt_k<<<ROWS, 64>>>(tokens, norm_w, xh, xl);
    // 2) in-proj GEMM (mma): 32768x256 @ 256x1064
    gemm_mma<<<dim3(NT1 / 128, ROWS / 128), 256, 2 * GSM_STAGE>>>(
        xh, xl, wt1h, wt1l, in_b, nullptr, zx, nullptr, nullptr, HID, PROJ);
    // 3) conv + silu
    conv_k<<<(ROWS * CCH + 255) / 256, 256>>>(zx, conv_w, conv_b, xbc);
    // 4) chunked scan
    scanA_k<<<dim3(NHH, BB, NC), 64>>>(xbc, zx, dt_bias, A_log, Dp, y, hloc, cum);
    scanB_k<<<dim3(NHH, BB), 64>>>(hloc, cum, hstart);
    scanC_k<<<dim3(NHH, BB, NC - 1), 64>>>(xbc, hstart, cum, y);
    // 5) gate + rmsnorm -> bf16 split
    gatenorm_cvt_k<<<ROWS, 128>>>(y, zx, gnorm_w, yh, yl);
    // 6) out-proj GEMM (mma) + residual, fused shift+cvt into ph/pl
    gemm_mma<<<dim3(HID / 128, ROWS / 128), 256, 2 * GSM_STAGE>>>(
        yh, yl, wt2h, wt2l, out_b, tokens, nullptr, ph, pl, DI, HID);
    // 7) Kalman GEMM -> finish
    gemm_mma<<<dim3(1, ROWS / 128), 256, 2 * GSM_STAGE>>>(
        ph, pl, wkh, wkl, kb, nullptr, ap, nullptr, nullptr, HID, 128);
    kalman_fin_k<<<ROWS, 64>>>(ap, z_t, kg_w1,
                               kp_w2, kp_b2, km_w1, km_b1, km_w2, km_b2,
                               kg_w2, kg_b2, kW, out);
    // 8) per-batch reductions
    reduce_k<<<BB, 256>>>(out);
}

// round 9
// speedup vs baseline: 2.1652x; 1.0738x over previous
#include <cuda_runtime.h>
#include <cuda_bf16.h>
#include <cstdint>

#define BB    64
#define TT    512
#define HID   256
#define DI    512
#define DS    16
#define NHH   8
#define HD    64
#define DCONV 4
#define CCH   544    // DI + 2*DS
#define PROJ  1064   // 2*DI + 2*DS + NH
#define ROWS  (BB*TT) // 32768
#define NC    16
#define LC    32     // TT/NC
#define NT1   1152   // PROJ padded to 9*128

// ---------------- scratch (device globals; no allocation allowed) ----------
__device__ __align__(16) float g_zx[ROWS * PROJ];
__device__ __align__(16) float g_y[ROWS * DI];
__device__ __align__(16) float g_bc[ROWS * 32];
__device__ __align__(16) float g_hloc[BB * NHH * NC * HD * DS];
__device__ __align__(16) float g_hstart[BB * NHH * NC * HD * DS];
__device__ __align__(16) float g_cum[BB * NHH * TT];
__device__ __align__(16) __nv_bfloat16 g_xh[ROWS * HID];
__device__ __align__(16) __nv_bfloat16 g_xl[ROWS * HID];
__device__ __align__(16) __nv_bfloat16 g_yh[ROWS * DI];
__device__ __align__(16) __nv_bfloat16 g_yl[ROWS * DI];
__device__ __align__(16) __nv_bfloat16 g_ph[ROWS * HID];
__device__ __align__(16) __nv_bfloat16 g_pl[ROWS * HID];
__device__ __align__(16) float g_ap[ROWS * 128];
__device__ __align__(16) __nv_bfloat16 g_wt1h[NT1 * HID];
__device__ __align__(16) __nv_bfloat16 g_wt1l[NT1 * HID];
__device__ __align__(16) __nv_bfloat16 g_wt2h[HID * DI];
__device__ __align__(16) __nv_bfloat16 g_wt2l[HID * DI];
__device__ __align__(16) __nv_bfloat16 g_wkh[128 * HID];
__device__ __align__(16) __nv_bfloat16 g_wkl[128 * HID];
__device__ __align__(16) float g_kb[128];

// ---------------- helpers ---------------------------------------------------
__device__ __forceinline__ float siluf(float x) { return x / (1.f + __expf(-x)); }
__device__ __forceinline__ float softplusf(float x) {
    return (x > 20.f) ? x : log1pf(__expf(x));
}
__device__ __forceinline__ float sigmoidf_(float x) { return 1.f / (1.f + __expf(-x)); }
__device__ __forceinline__ float warpSum(float v) {
#pragma unroll
    for (int o = 16; o; o >>= 1) v += __shfl_xor_sync(0xffffffffu, v, o);
    return v;
}
__device__ __forceinline__ void bf16split(float v, __nv_bfloat16* h, __nv_bfloat16* l) {
    __nv_bfloat16 hi = __float2bfloat16(v);
    *h = hi;
    *l = __float2bfloat16(v - __bfloat162float(hi));
}
__device__ __forceinline__ uint32_t smem_u32(const void* p) {
    uint32_t a;
    asm("{ .reg .u64 t; cvta.to.shared.u64 t, %1; cvt.u32.u64 %0, t; }"
        : "=r"(a) : "l"(p));
    return a;
}
#define SWZ(b) ((b) ^ (((b) >> 3) & 0x70))

__device__ __forceinline__ void ldsm_x4(uint32_t* r, uint32_t addr) {
    asm volatile("ldmatrix.sync.aligned.m8n8.x4.shared.b16 {%0,%1,%2,%3}, [%4];"
                 : "=r"(r[0]), "=r"(r[1]), "=r"(r[2]), "=r"(r[3]) : "r"(addr));
}
__device__ __forceinline__ void mma16816(float* c, const uint32_t* a, const uint32_t* b) {
    asm volatile("mma.sync.aligned.m16n8k16.row.col.f32.bf16.bf16.f32 "
                 "{%0,%1,%2,%3}, {%4,%5,%6,%7}, {%8,%9}, {%0,%1,%2,%3};"
                 : "+f"(c[0]), "+f"(c[1]), "+f"(c[2]), "+f"(c[3])
                 : "r"(a[0]), "r"(a[1]), "r"(a[2]), "r"(a[3]), "r"(b[0]), "r"(b[1]));
}
#define CP16(sa, gp) \
    asm volatile("cp.async.cg.shared.global [%0], [%1], 16;" :: "r"(sa), "l"(gp))
#define CP_COMMIT() asm volatile("cp.async.commit_group;" ::: "memory")
#define CP_WAIT1() asm volatile("cp.async.wait_group 1;" ::: "memory")
#define CP_WAIT0() asm volatile("cp.async.wait_group 0;" ::: "memory")

// ---------------- bf16 split GEMM via mma.sync, cp.async 2-stage ------------
#define GSM_STAGE 32768
__global__ __launch_bounds__(256) void gemm_mma(
    const __nv_bfloat16* __restrict__ Ah, const __nv_bfloat16* __restrict__ Al,
    const __nv_bfloat16* __restrict__ Bh, const __nv_bfloat16* __restrict__ Bl,
    const float* __restrict__ bias, const float* __restrict__ res,
    float* __restrict__ C,
    __nv_bfloat16* __restrict__ oh, __nv_bfloat16* __restrict__ ol,
    int K, int N)
{
    extern __shared__ __align__(16) uint8_t dsm[];
    uint32_t sbase = smem_u32(dsm);

    int tid = threadIdx.x;
    int wid = tid >> 5, lane = tid & 31;
    int bm = blockIdx.y * 128, bn = blockIdx.x * 128;
    int wm = (wid >> 2) * 64;
    int wn = (wid & 3) * 32;

    int lrow = tid >> 1;
    int lke  = (tid & 1) * 16;
    const __nv_bfloat16* pAh = Ah + (size_t)(bm + lrow) * K + lke;
    const __nv_bfloat16* pAl = Al + (size_t)(bm + lrow) * K + lke;
    const __nv_bfloat16* pBh = Bh + (size_t)(bn + lrow) * K + lke;
    const __nv_bfloat16* pBl = Bl + (size_t)(bn + lrow) * K + lke;
    uint32_t so0 = SWZ((uint32_t)(lrow * 64 + lke * 2));
    uint32_t so1 = SWZ((uint32_t)(lrow * 64 + lke * 2 + 16));

    float acc[4][4][4];
#pragma unroll
    for (int i = 0; i < 4; i++)
#pragma unroll
        for (int j = 0; j < 4; j++)
#pragma unroll
            for (int q = 0; q < 4; q++) acc[i][j][q] = 0.f;

    int aRow = lane & 15;
    int aKb  = (lane >> 4) << 4;
    int bRow = ((lane >> 4) << 3) + (lane & 7);
    int bKb  = ((lane >> 3) & 1) << 4;

    const int KC = K >> 5;

    {
        uint32_t st = sbase;
        CP16(st + so0,         pAh);      CP16(st + so1,         pAh + 8);
        CP16(st + 8192 + so0,  pAl);      CP16(st + 8192 + so1,  pAl + 8);
        CP16(st + 16384 + so0, pBh);      CP16(st + 16384 + so1, pBh + 8);
        CP16(st + 24576 + so0, pBl);      CP16(st + 24576 + so1, pBl + 8);
        CP_COMMIT();
    }

    for (int c = 0; c < KC; c++) {
        if (c + 1 < KC) {
            int e = (c + 1) * 32;
            uint32_t st = sbase + ((c + 1) & 1) * GSM_STAGE;
            CP16(st + so0,         pAh + e);   CP16(st + so1,         pAh + e + 8);
            CP16(st + 8192 + so0,  pAl + e);   CP16(st + 8192 + so1,  pAl + e + 8);
            CP16(st + 16384 + so0, pBh + e);   CP16(st + 16384 + so1, pBh + e + 8);
            CP16(st + 24576 + so0, pBl + e);   CP16(st + 24576 + so1, pBl + e + 8);
            CP_COMMIT();
            CP_WAIT1();
        } else {
            CP_WAIT0();
        }
        __syncthreads();

        uint32_t st = sbase + (c & 1) * GSM_STAGE;
        uint32_t sbAH = st, sbAL = st + 8192, sbBH = st + 16384, sbBL = st + 24576;

#pragma unroll
        for (int ks = 0; ks < 2; ks++) {
            int kb = ks * 32;
            uint32_t ah[4][4], al[4][4], bh[2][4], bl[2][4];
#pragma unroll
            for (int mt = 0; mt < 4; mt++) {
                uint32_t off = SWZ((uint32_t)(wm + mt * 16 + aRow) * 64 + kb + aKb);
                ldsm_x4(ah[mt], sbAH + off);
                ldsm_x4(al[mt], sbAL + off);
            }
#pragma unroll
            for (int np = 0; np < 2; np++) {
                uint32_t off = SWZ((uint32_t)(wn + np * 16 + bRow) * 64 + kb + bKb);
                ldsm_x4(bh[np], sbBH + off);
                ldsm_x4(bl[np], sbBL + off);
            }
#pragma unroll
            for (int mt = 0; mt < 4; mt++) {
#pragma unroll
                for (int nt = 0; nt < 4; nt++) {
                    const uint32_t* pbh = &bh[nt >> 1][(nt & 1) * 2];
                    const uint32_t* pbl = &bl[nt >> 1][(nt & 1) * 2];
                    mma16816(acc[mt][nt], ah[mt], pbh);
                    mma16816(acc[mt][nt], ah[mt], pbl);
                    mma16816(acc[mt][nt], al[mt], pbh);
                }
            }
        }
        __syncthreads();
    }

    int mrow0 = bm + wm + (lane >> 2);
    int ncol0 = bn + wn + (lane & 3) * 2;
#pragma unroll
    for (int mt = 0; mt < 4; mt++) {
#pragma unroll
        for (int half = 0; half < 2; half++) {
            int m = mrow0 + mt * 16 + half * 8;
            float* crow = C ? C + (size_t)m * N : nullptr;
            const float* rrow = res ? res + (size_t)m * N : nullptr;
            int mp = m + 1;
            bool doshift = (oh != nullptr) && ((mp & (TT - 1)) != 0);
#pragma unroll
            for (int nt = 0; nt < 4; nt++) {
                int n = ncol0 + nt * 8;
                if (n + 1 < N) {
                    float v0 = acc[mt][nt][half * 2 + 0] + bias[n];
                    float v1 = acc[mt][nt][half * 2 + 1] + bias[n + 1];
                    if (res) { v0 += rrow[n]; v1 += rrow[n + 1]; }
                    if (crow) { crow[n] = v0; crow[n + 1] = v1; }
                    if (doshift) {
                        __nv_bfloat16 h0, l0, h1, l1;
                        bf16split(v0, &h0, &l0);
                        bf16split(v1, &h1, &l1);
                        __nv_bfloat162 hp, lp;
                        hp.x = h0; hp.y = h1; lp.x = l0; lp.y = l1;
                        *(__nv_bfloat162*)(oh + (size_t)mp * N + n) = hp;
                        *(__nv_bfloat162*)(ol + (size_t)mp * N + n) = lp;
                    }
                } else if (n < N) {
                    float v0 = acc[mt][nt][half * 2 + 0] + bias[n];
                    if (res) v0 += rrow[n];
                    if (crow) crow[n] = v0;
                }
            }
        }
    }
}

// ---------------- merged weight prep + t=0 Kalman rows ----------------------
#define W1SZ (NT1 * HID)
#define W2SZ (HID * DI)
#define WKSZ (128 * HID)
__global__ void prep_k(const float* __restrict__ in_w, const float* __restrict__ out_w,
                       const float* __restrict__ kp_w1, const float* __restrict__ kg_w1,
                       const float* __restrict__ kp_b1, const float* __restrict__ kg_b1,
                       __nv_bfloat16* __restrict__ w1h, __nv_bfloat16* __restrict__ w1l,
                       __nv_bfloat16* __restrict__ w2h, __nv_bfloat16* __restrict__ w2l,
                       __nv_bfloat16* __restrict__ wkh, __nv_bfloat16* __restrict__ wkl,
                       float* __restrict__ kb) {
    int idx = blockIdx.x * blockDim.x + threadIdx.x;
    if (idx < W1SZ) {
        int n = idx / HID, k = idx % HID;
        float v = (n < PROJ) ? in_w[(size_t)k * PROJ + n] : 0.f;
        bf16split(v, &w1h[idx], &w1l[idx]);
    } else if (idx < W1SZ + W2SZ) {
        int i = idx - W1SZ;
        int n = i / DI, k = i % DI;
        bf16split(out_w[(size_t)k * HID + n], &w2h[i], &w2l[i]);
    } else if (idx < W1SZ + W2SZ + WKSZ) {
        int i = idx - W1SZ - W2SZ;
        int n = i / HID, k = i % HID;
        float v = (n < 64) ? kp_w1[(size_t)k * 64 + n] : kg_w1[(size_t)k * 64 + (n - 64)];
        bf16split(v, &wkh[i], &wkl[i]);
        if (i < 128) kb[i] = (i < 64) ? kp_b1[i] : kg_b1[i - 64];
    }
}

__global__ void initrow_k(const float* __restrict__ init_state,
                          __nv_bfloat16* __restrict__ oh, __nv_bfloat16* __restrict__ ol) {
    int b = blockIdx.x;
    int tid = threadIdx.x;
    float4 v = ((const float4*)init_state)[tid];
    float o[4] = {v.x, v.y, v.z, v.w};
    __nv_bfloat16 hh[4], ll[4];
#pragma unroll
    for (int i = 0; i < 4; i++) bf16split(o[i], &hh[i], &ll[i]);
    size_t base = (size_t)(b * TT) * HID + tid * 4;
    *(uint2*)(oh + base) = *(uint2*)hh;
    *(uint2*)(ol + base) = *(uint2*)ll;
}

// ---------------- 1) rmsnorm -> bf16 hi/lo (warp per row) -------------------
__global__ void rmsnorm_cvt_k(const float* __restrict__ x, const float* __restrict__ w,
                              __nv_bfloat16* __restrict__ oh, __nv_bfloat16* __restrict__ ol) {
    int r = blockIdx.x * 4 + (threadIdx.x >> 5);
    int lane = threadIdx.x & 31;
    const float4* xr = (const float4*)(x + (size_t)r * HID);
    float4 v0 = xr[lane], v1 = xr[lane + 32];
    float ss = v0.x*v0.x + v0.y*v0.y + v0.z*v0.z + v0.w*v0.w
             + v1.x*v1.x + v1.y*v1.y + v1.z*v1.z + v1.w*v1.w;
    ss = warpSum(ss);
    float sc = rsqrtf(ss / HID + 1e-5f);
    const float4* wr = (const float4*)w;
    float4 w0 = wr[lane], w1 = wr[lane + 32];
    float o0[4] = {v0.x*sc*w0.x, v0.y*sc*w0.y, v0.z*sc*w0.z, v0.w*sc*w0.w};
    float o1[4] = {v1.x*sc*w1.x, v1.y*sc*w1.y, v1.z*sc*w1.z, v1.w*sc*w1.w};
    __nv_bfloat16 h0[4], l0[4], h1[4], l1[4];
#pragma unroll
    for (int i = 0; i < 4; i++) { bf16split(o0[i], &h0[i], &l0[i]); bf16split(o1[i], &h1[i], &l1[i]); }
    size_t base = (size_t)r * HID;
    *(uint2*)(oh + base + lane * 4) = *(uint2*)h0;
    *(uint2*)(oh + base + (lane + 32) * 4) = *(uint2*)h1;
    *(uint2*)(ol + base + lane * 4) = *(uint2*)l0;
    *(uint2*)(ol + base + (lane + 32) * 4) = *(uint2*)l1;
}

// ---------------- 4a) fused conv+silu + chunked scan local pass -------------
__global__ __launch_bounds__(64) void scanA_k(
    const float* __restrict__ zx, const float* __restrict__ cw,
    const float* __restrict__ cbv,
    const float* __restrict__ dt_bias, const float* __restrict__ A_log,
    const float* __restrict__ Dp, float* __restrict__ y,
    float* __restrict__ hloc, float* __restrict__ cum, float* __restrict__ bc)
{
    __shared__ float sBC[LC][32];
    __shared__ float sdt[LC];
    int h = blockIdx.x, b = blockIdx.y, c = blockIdx.z;
    int d = threadIdx.x;
    int t0 = c * LC;
    size_t rowbase = (size_t)(b * TT + t0);

    // B/C with inline conv (channels 512..543 of xBC)
    for (int i = d; i < LC * 32; i += 64) {
        int t = i >> 5, j = i & 31;
        int ch = 512 + j;
        float acc = cbv[ch];
#pragma unroll
        for (int k = 0; k < DCONV; k++) {
            int tt = t0 + t - (DCONV - 1) + k;
            if (tt >= 0)
                acc = fmaf(zx[((size_t)(b * TT + tt)) * PROJ + DI + ch],
                           cw[k * CCH + ch], acc);
        }
        float v = siluf(acc);
        sBC[t][j] = v;
        if (h == 0) bc[(rowbase + t) * 32 + j] = v;
    }
    float dtb = dt_bias[h];
    for (int i = d; i < LC; i += 64)
        sdt[i] = softplusf(zx[(rowbase + i) * PROJ + 2 * DI + 2 * DS + h] + dtb);
    __syncthreads();

    // x-channel conv (rolling window)
    int ch = h * HD + d;
    float w0 = cw[0 * CCH + ch], w1 = cw[1 * CCH + ch];
    float w2 = cw[2 * CCH + ch], w3 = cw[3 * CCH + ch];
    float cb0 = cbv[ch];
    const float* xcol = zx + DI + ch;
    float r0 = 0.f, r1 = 0.f, r2 = 0.f;
    {
        int tb = t0 - 3;
        if (tb >= 0)     r0 = xcol[(size_t)(b * TT + tb) * PROJ];
        if (tb + 1 >= 0) r1 = xcol[(size_t)(b * TT + tb + 1) * PROJ];
        if (tb + 2 >= 0) r2 = xcol[(size_t)(b * TT + tb + 2) * PROJ];
    }

    float A = -__expf(A_log[h]);
    float Dh = Dp[h];
    float hr[DS];
#pragma unroll
    for (int s = 0; s < DS; s++) hr[s] = 0.f;
    float cm = 1.f;

    float* yp = y + rowbase * DI + h * HD + d;
    float* cmp = cum + ((size_t)(b * NHH + h)) * TT + t0;

    for (int t = 0; t < LC; t++) {
        float raw = xcol[(rowbase + t) * PROJ];
        float x = siluf(fmaf(raw, w3, fmaf(r2, w2, fmaf(r1, w1, fmaf(r0, w0, cb0)))));
        r0 = r1; r1 = r2; r2 = raw;

        float dtsp = sdt[t];
        float dA = __expf(dtsp * A);
        cm *= dA;
        if (d == 0) cmp[t] = cm;
        float dtx = dtsp * x;
        float yvp[4] = {Dh * x, 0.f, 0.f, 0.f};
        float Bv[16], Cv[16];
        *(float4*)&Bv[0]  = *(const float4*)&sBC[t][0];
        *(float4*)&Bv[4]  = *(const float4*)&sBC[t][4];
        *(float4*)&Bv[8]  = *(const float4*)&sBC[t][8];
        *(float4*)&Bv[12] = *(const float4*)&sBC[t][12];
        *(float4*)&Cv[0]  = *(const float4*)&sBC[t][16];
        *(float4*)&Cv[4]  = *(const float4*)&sBC[t][20];
        *(float4*)&Cv[8]  = *(const float4*)&sBC[t][24];
        *(float4*)&Cv[12] = *(const float4*)&sBC[t][28];
#pragma unroll
        for (int s = 0; s < DS; s++) {
            hr[s] = fmaf(hr[s], dA, dtx * Bv[s]);
            yvp[s & 3] = fmaf(hr[s], Cv[s], yvp[s & 3]);
        }
        yp[(size_t)t * DI] = (yvp[0] + yvp[1]) + (yvp[2] + yvp[3]);
    }

    float* hl = hloc + ((size_t)((b * NHH + h) * NC + c)) * (DS * HD);
#pragma unroll
    for (int s = 0; s < DS; s++) hl[s * HD + d] = hr[s];
}

// ---------------- 4b) chain chunk states ------------------------------------
__global__ __launch_bounds__(64) void scanB_k(const float* __restrict__ hloc,
                                              const float* __restrict__ cum,
                                              float* __restrict__ hstart)
{
    int h = blockIdx.x, b = blockIdx.y, d = threadIdx.x;
    size_t base = (size_t)(b * NHH + h);
    float hs[DS];
#pragma unroll
    for (int s = 0; s < DS; s++) hs[s] = 0.f;
    for (int c = 0; c < NC; c++) {
        float* hsp = hstart + (base * NC + c) * (DS * HD);
#pragma unroll
        for (int s = 0; s < DS; s++) hsp[s * HD + d] = hs[s];
        float P = cum[base * TT + c * LC + LC - 1];
        const float* hl = hloc + (base * NC + c) * (DS * HD);
#pragma unroll
        for (int s = 0; s < DS; s++) hs[s] = fmaf(hs[s], P, hl[s * HD + d]);
    }
}

// ---------------- 4c) correction --------------------------------------------
__global__ __launch_bounds__(64) void scanC_k(const float* __restrict__ bc,
                                              const float* __restrict__ hstart,
                                              const float* __restrict__ cum,
                                              float* __restrict__ y)
{
    __shared__ float sC[LC][16];
    __shared__ float scm[LC];
    int h = blockIdx.x, b = blockIdx.y, c = blockIdx.z + 1;
    int d = threadIdx.x;
    int t0 = c * LC;
    size_t rowbase = (size_t)(b * TT + t0);
    size_t base = (size_t)(b * NHH + h);

    for (int i = d; i < LC * 16; i += 64) {
        int t = i >> 4, j = i & 15;
        sC[t][j] = bc[(rowbase + t) * 32 + 16 + j];
    }
    for (int i = d; i < LC; i += 64) scm[i] = cum[base * TT + t0 + i];

    float hs[DS];
    const float* hsp = hstart + (base * NC + c) * (DS * HD);
#pragma unroll
    for (int s = 0; s < DS; s++) hs[s] = hsp[s * HD + d];
    __syncthreads();

    float* yp = y + rowbase * DI + h * HD + d;
    for (int t = 0; t < LC; t++) {
        float Cv[16];
        *(float4*)&Cv[0]  = *(const float4*)&sC[t][0];
        *(float4*)&Cv[4]  = *(const float4*)&sC[t][4];
        *(float4*)&Cv[8]  = *(const float4*)&sC[t][8];
        *(float4*)&Cv[12] = *(const float4*)&sC[t][12];
        float acc = 0.f;
#pragma unroll
        for (int s = 0; s < DS; s++) acc = fmaf(hs[s], Cv[s], acc);
        yp[(size_t)t * DI] += acc * scm[t];
    }
}

// ---------------- 5) gate + rmsnorm -> bf16 (warp per row) ------------------
__global__ void gatenorm_cvt_k(const float* __restrict__ y, const float* __restrict__ zx,
                               const float* __restrict__ gw,
                               __nv_bfloat16* __restrict__ oh, __nv_bfloat16* __restrict__ ol) {
    int r = blockIdx.x * 4 + (threadIdx.x >> 5);
    int lane = threadIdx.x & 31;
    const float4* yr = (const float4*)(y + (size_t)r * DI);
    const float4* zr = (const float4*)(zx + (size_t)r * PROJ);
    float4 g[4];
    float ss = 0.f;
#pragma unroll
    for (int k = 0; k < 4; k++) {
        float4 yv = yr[lane + 32 * k];
        float4 zv = zr[lane + 32 * k];
        g[k].x = yv.x * siluf(zv.x); g[k].y = yv.y * siluf(zv.y);
        g[k].z = yv.z * siluf(zv.z); g[k].w = yv.w * siluf(zv.w);
        ss += g[k].x*g[k].x + g[k].y*g[k].y + g[k].z*g[k].z + g[k].w*g[k].w;
    }
    ss = warpSum(ss);
    float sc = rsqrtf(ss / DI + 1e-5f);
    const float4* wr = (const float4*)gw;
    size_t base = (size_t)r * DI;
#pragma unroll
    for (int k = 0; k < 4; k++) {
        float4 wv = wr[lane + 32 * k];
        float o[4] = {g[k].x*sc*wv.x, g[k].y*sc*wv.y, g[k].z*sc*wv.z, g[k].w*sc*wv.w};
        __nv_bfloat16 hh[4], ll[4];
#pragma unroll
        for (int i = 0; i < 4; i++) bf16split(o[i], &hh[i], &ll[i]);
        *(uint2*)(oh + base + (lane + 32 * k) * 4) = *(uint2*)hh;
        *(uint2*)(ol + base + (lane + 32 * k) * 4) = *(uint2*)ll;
    }
}

// ---------------- 7b) Kalman finish -----------------------------------------
__global__ __launch_bounds__(64) void kalman_fin_k(
    const float* __restrict__ AP, const float* __restrict__ z_t,
    const float* __restrict__ kg_w1,
    const float* __restrict__ kp_w2, const float* __restrict__ kp_b2,
    const float* __restrict__ km_w1, const float* __restrict__ km_b1,
    const float* __restrict__ km_w2, const float* __restrict__ km_b2,
    const float* __restrict__ kg_w2, const float* __restrict__ kg_b2,
    const float* __restrict__ kW, float* __restrict__ out)
{
    __shared__ float redv[2], redg[2];
    int r = blockIdx.x;
    int tid = threadIdx.x;
    float z = z_t[r];
    float ap = AP[(size_t)r * 128 + tid];
    float ag = AP[(size_t)r * 128 + 64 + tid];
    ag = fmaf(z, kg_w1[HID * 64 + tid], ag);
    float vp = siluf(ap) * kp_w2[tid];
    float gp = siluf(ag) * kg_w2[tid];
    vp = warpSum(vp);
    gp = warpSum(gp);
    if ((tid & 31) == 0) { redv[tid >> 5] = vp; redg[tid >> 5] = gp; }
    __syncthreads();
    if (tid == 0) {
        float v_prior = softplusf(redv[0] + redv[1] + kp_b2[0]);
        float Kt = sigmoidf_(redg[0] + redg[1] + kg_b2[0]);
        float macc = km_b2[0];
#pragma unroll
        for (int k = 0; k < 32; k++)
            macc = fmaf(siluf(fmaf(z, km_w1[k], km_b1[k])), km_w2[k], macc);
        float m_t = softplusf(macc);
        float vpost = v_prior + Kt * (m_t - kW[0] * v_prior);
        vpost = fminf(fmaxf(vpost, 1e-6f), 10.f);
        out[r] = vpost;
    }
}

// ---------------- 8) per-batch softmax reductions ---------------------------
__global__ void reduce_k(float* __restrict__ out) {
    __shared__ float sa[256], sb[256];
    int b = blockIdx.x;
    int tid = threadIdx.x;
    const float* v = out + (size_t)b * TT;
    float v0 = v[tid], v1 = v[tid + 256];

    sa[tid] = fmaxf(v0, v1);
    sb[tid] = fminf(v0, v1);
    __syncthreads();
    for (int s = 128; s > 0; s >>= 1) {
        if (tid < s) {
            sa[tid] = fmaxf(sa[tid], sa[tid + s]);
            sb[tid] = fminf(sb[tid], sb[tid + s]);
        }
        __syncthreads();
    }
    float mx = sa[0], mn = sb[0];
    __syncthreads();

    float e0 = __expf(v0 - mx), e1 = __expf(v1 - mx);
    sa[tid] = e0 + e1;
    sb[tid] = e0 * v0 + e1 * v1;
    __syncthreads();
    for (int s = 128; s > 0; s >>= 1) {
        if (tid < s) { sa[tid] += sa[tid + s]; sb[tid] += sb[tid + s]; }
        __syncthreads();
    }
    float spden = sa[0], spnum = sb[0];
    __syncthreads();

    float f0 = __expf(mn - v0), f1 = __expf(mn - v1);
    sa[tid] = f0 + f1;
    sb[tid] = f0 * v0 + f1 * v1;
    __syncthreads();
    for (int s = 128; s > 0; s >>= 1) {
        if (tid < s) { sa[tid] += sa[tid + s]; sb[tid] += sb[tid + s]; }
        __syncthreads();
    }
    if (tid == 0) {
        out[ROWS + b] = spnum / spden;
        out[ROWS + BB + b] = sb[0] / sa[0];
    }
}

// ---------------- launcher ---------------------------------------------------
extern "C" void kernel_launch(void* const* d_in, const int* in_sizes, int n_in,
                              void* d_out, int out_size) {
    const float* tokens   = (const float*)d_in[0];
    const float* z_t      = (const float*)d_in[1];
    const float* norm_w   = (const float*)d_in[2];
    const float* in_w     = (const float*)d_in[3];
    const float* in_b     = (const float*)d_in[4];
    const float* conv_w   = (const float*)d_in[5];
    const float* conv_b   = (const float*)d_in[6];
    const float* dt_bias  = (const float*)d_in[7];
    const float* A_log    = (const float*)d_in[8];
    const float* Dp       = (const float*)d_in[9];
    const float* gnorm_w  = (const float*)d_in[10];
    const float* out_w    = (const float*)d_in[11];
    const float* out_b    = (const float*)d_in[12];
    const float* kp_w1    = (const float*)d_in[13];
    const float* kp_b1    = (const float*)d_in[14];
    const float* kp_w2    = (const float*)d_in[15];
    const float* kp_b2    = (const float*)d_in[16];
    const float* km_w1    = (const float*)d_in[17];
    const float* km_b1    = (const float*)d_in[18];
    const float* km_w2    = (const float*)d_in[19];
    const float* km_b2    = (const float*)d_in[20];
    const float* kg_w1    = (const float*)d_in[21];
    const float* kg_b1    = (const float*)d_in[22];
    const float* kg_w2    = (const float*)d_in[23];
    const float* kg_b2    = (const float*)d_in[24];
    const float* kW       = (const float*)d_in[25];
    const float* init_st  = (const float*)d_in[26];
    float* out = (float*)d_out;

    float *zx, *y, *bc, *hloc, *hstart, *cum, *ap, *kb;
    __nv_bfloat16 *xh, *xl, *yh, *yl, *ph, *pl, *wt1h, *wt1l, *wt2h, *wt2l, *wkh, *wkl;
    cudaGetSymbolAddress((void**)&zx,     g_zx);
    cudaGetSymbolAddress((void**)&y,      g_y);
    cudaGetSymbolAddress((void**)&bc,     g_bc);
    cudaGetSymbolAddress((void**)&hloc,   g_hloc);
    cudaGetSymbolAddress((void**)&hstart, g_hstart);
    cudaGetSymbolAddress((void**)&cum,    g_cum);
    cudaGetSymbolAddress((void**)&ap,     g_ap);
    cudaGetSymbolAddress((void**)&kb,     g_kb);
    cudaGetSymbolAddress((void**)&xh,     g_xh);
    cudaGetSymbolAddress((void**)&xl,     g_xl);
    cudaGetSymbolAddress((void**)&yh,     g_yh);
    cudaGetSymbolAddress((void**)&yl,     g_yl);
    cudaGetSymbolAddress((void**)&ph,     g_ph);
    cudaGetSymbolAddress((void**)&pl,     g_pl);
    cudaGetSymbolAddress((void**)&wt1h,   g_wt1h);
    cudaGetSymbolAddress((void**)&wt1l,   g_wt1l);
    cudaGetSymbolAddress((void**)&wt2h,   g_wt2h);
    cudaGetSymbolAddress((void**)&wt2l,   g_wt2l);
    cudaGetSymbolAddress((void**)&wkh,    g_wkh);
    cudaGetSymbolAddress((void**)&wkl,    g_wkl);

    cudaFuncSetAttribute(gemm_mma, cudaFuncAttributeMaxDynamicSharedMemorySize,
                         2 * GSM_STAGE);

    // weight prep (merged) + t=0 Kalman rows
    prep_k<<<(W1SZ + W2SZ + WKSZ + 255) / 256, 256>>>(
        in_w, out_w, kp_w1, kg_w1, kp_b1, kg_b1,
        wt1h, wt1l, wt2h, wt2l, wkh, wkl, kb);
    initrow_k<<<BB, 64>>>(init_st, ph, pl);

    // 1) rmsnorm -> bf16 split (warp per row)
    rmsnorm_cvt_k<<<ROWS / 4, 128>>>(tokens, norm_w, xh, xl);
    // 2) in-proj GEMM
    gemm_mma<<<dim3(NT1 / 128, ROWS / 128), 256, 2 * GSM_STAGE>>>(
        xh, xl, wt1h, wt1l, in_b, nullptr, zx, nullptr, nullptr, HID, PROJ);
    // 3+4) fused conv + chunked scan
    scanA_k<<<dim3(NHH, BB, NC), 64>>>(zx, conv_w, conv_b, dt_bias, A_log, Dp,
                                       y, hloc, cum, bc);
    scanB_k<<<dim3(NHH, BB), 64>>>(hloc, cum, hstart);
    scanC_k<<<dim3(NHH, BB, NC - 1), 64>>>(bc, hstart, cum, y);
    // 5) gate + rmsnorm (warp per row)
    gatenorm_cvt_k<<<ROWS / 4, 128>>>(y, zx, gnorm_w, yh, yl);
    // 6) out-proj GEMM + residual, fused shift+cvt into ph/pl
    gemm_mma<<<dim3(HID / 128, ROWS / 128), 256, 2 * GSM_STAGE>>>(
        yh, yl, wt2h, wt2l, out_b, tokens, nullptr, ph, pl, DI, HID);
    // 7) Kalman GEMM -> finish
    gemm_mma<<<dim3(1, ROWS / 128), 256, 2 * GSM_STAGE>>>(
        ph, pl, wkh, wkl, kb, nullptr, ap, nullptr, nullptr, HID, 128);
    kalman_fin_k<<<ROWS, 64>>>(ap, z_t, kg_w1,
                               kp_w2, kp_b2, km_w1, km_b1, km_w2, km_b2,
                               kg_w2, kg_b2, kW, out);
    // 8) per-batch reductions
    reduce_k<<<BB, 256>>>(out);
}